// round 13
// baseline (speedup 1.0000x reference)
#include <cuda_runtime.h>
#include <cuda_fp16.h>
#include <cstdint>
#include <cstddef>

#define NN 4096
#define CC 128
#define BB 4
#define NEGV (-9e15f)
#define LOG2E 1.4426950408889634f
#define FSCALE 256.0f

typedef unsigned long long ull;

// ---------------- scratch (device globals: no allocation allowed) -----------
__device__ float  g_h[(size_t)BB * CC * NN];                 // 8 MB
__device__ float  g_y[(size_t)BB * CC * NN];                 // 8 MB
__device__ __half g_qh[(size_t)BB * 32 * NN];                // 1 MB
__device__ __half g_ql[(size_t)BB * 32 * NN];                // 1 MB
__device__ __half g_qth[(size_t)BB * NN * 32];               // 1 MB
__device__ __half g_qtl[(size_t)BB * NN * 32];               // 1 MB
__device__ __half g_xvh[(size_t)BB * CC * NN];               // 4 MB
__device__ float  g_xr[(size_t)BB * CC * NN];                // 8 MB
__device__ float  g_tmax[(size_t)32 * BB * NN];
__device__ float  g_tsum[(size_t)32 * BB * NN];
__device__ float  g_rm[(size_t)BB * NN];                     // global row max
__device__ float  g_fs[(size_t)BB * NN];                     // FSCALE / rowsum
__device__ float  g_scale[CC];
__device__ float  g_shift[CC];
__device__ float  g_bnpS[64][BB][CC];
__device__ float  g_bnpQ[64][BB][CC];

// ---------------- helpers ----------------------------------------------------
__device__ __forceinline__ void fma2(ull& acc, ull a, ull b) {
    asm("fma.rn.f32x2 %0, %1, %2, %0;" : "+l"(acc) : "l"(a), "l"(b));
}
__device__ __forceinline__ ull pack2(float v) {
    ull r;
    unsigned u = __float_as_uint(v);
    asm("mov.b64 %0, {%1, %1};" : "=l"(r) : "r"(u));
    return r;
}
__device__ __forceinline__ float2 unpack2(ull v) {
    unsigned lo, hi;
    asm("mov.b64 {%0, %1}, %2;" : "=r"(lo), "=r"(hi) : "l"(v));
    return make_float2(__uint_as_float(lo), __uint_as_float(hi));
}
__device__ __forceinline__ __half2 h2_ex2(__half2 x) {
    unsigned xi = *(unsigned*)&x;
    unsigned ri;
    asm("ex2.approx.f16x2 %0, %1;" : "=r"(ri) : "r"(xi));
    return *(__half2*)&ri;
}
__device__ __forceinline__ void split2(float a, float b, __half2& h, __half2& l) {
    __half ha = __float2half_rn(a), hb = __float2half_rn(b);
    __half la = __float2half_rn(a - __half2float(ha));
    __half lb = __float2half_rn(b - __half2float(hb));
    h = __halves2half2(ha, hb);
    l = __halves2half2(la, lb);
}

// ---------------- HMMA helpers -------------------------------------------------
__device__ __forceinline__ void ldsm_x4(unsigned& r0, unsigned& r1, unsigned& r2, unsigned& r3,
                                        const void* p) {
    unsigned addr = (unsigned)__cvta_generic_to_shared(p);
    asm volatile("ldmatrix.sync.aligned.m8n8.x4.shared.b16 {%0,%1,%2,%3}, [%4];"
        : "=r"(r0), "=r"(r1), "=r"(r2), "=r"(r3) : "r"(addr));
}
__device__ __forceinline__ void ldsm_x4_t(unsigned& r0, unsigned& r1, unsigned& r2, unsigned& r3,
                                          const void* p) {
    unsigned addr = (unsigned)__cvta_generic_to_shared(p);
    asm volatile("ldmatrix.sync.aligned.m8n8.x4.trans.shared.b16 {%0,%1,%2,%3}, [%4];"
        : "=r"(r0), "=r"(r1), "=r"(r2), "=r"(r3) : "r"(addr));
}
__device__ __forceinline__ void mma16816(float d[4], const unsigned a[4], const unsigned b[2]) {
    asm volatile("mma.sync.aligned.m16n8k16.row.col.f32.f16.f16.f32 "
        "{%0,%1,%2,%3}, {%4,%5,%6,%7}, {%8,%9}, {%0,%1,%2,%3};"
        : "+f"(d[0]), "+f"(d[1]), "+f"(d[2]), "+f"(d[3])
        : "r"(a[0]), "r"(a[1]), "r"(a[2]), "r"(a[3]), "r"(b[0]), "r"(b[1]));
}

// ---------------- gemm_qk: q = Wqk (32xC) * X; FMA2; fp16 hi/lo + transposed ---
__global__ __launch_bounds__(256, 3) void gemm_qk(
    const float* __restrict__ W, const float* __restrict__ X,
    __half* __restrict__ QH, __half* __restrict__ QL,
    __half* __restrict__ QTH, __half* __restrict__ QTL)
{
    __shared__ float Ws[CC][36];
    __shared__ __align__(16) double Xd[64][34];

    const int b  = blockIdx.z;
    const int n0 = blockIdx.x * 64;
    const int tid = threadIdx.x;
    const int to = tid >> 4;
    const int tp = tid & 15;

    for (int idx = tid; idx < 32 * CC; idx += 256) {
        int o = idx / CC, c = idx % CC;
        Ws[c][o] = W[(size_t)o * CC + c];
    }

    const float* x1 = X + (size_t)b * CC * NN;

    ull acc[2][2];
    acc[0][0] = acc[0][1] = acc[1][0] = acc[1][1] = 0ull;

    for (int c0 = 0; c0 < CC; c0 += 64) {
        __syncthreads();
#pragma unroll
        for (int t = 0; t < 4; t++) {
            int idx = tid + t * 256;
            int c = idx >> 4, q = idx & 15;
            float4 v = *(const float4*)&x1[(size_t)(c0 + c) * NN + n0 + q * 4];
            *(double2*)&Xd[c][q * 2] = *(const double2*)&v;
        }
        __syncthreads();
#pragma unroll 8
        for (int k = 0; k < 64; k++) {
            float2 w2 = *(const float2*)&Ws[c0 + k][to * 2];
            ull xc0 = pack2(w2.x), xc1 = pack2(w2.y);
            double2 ad = *(const double2*)&Xd[k][2 * tp];
            ull a0 = *(const ull*)&ad.x;
            ull a1 = *(const ull*)&ad.y;
            fma2(acc[0][0], xc0, a0); fma2(acc[0][1], xc0, a1);
            fma2(acc[1][0], xc1, a0); fma2(acc[1][1], xc1, a1);
        }
    }

    __half h[2][2][2], l[2][2][2];
#pragma unroll
    for (int i = 0; i < 2; i++)
#pragma unroll
        for (int j = 0; j < 2; j++) {
            float2 v = unpack2(acc[i][j]);
            h[i][j][0] = __float2half_rn(v.x);
            l[i][j][0] = __float2half_rn(v.x - __half2float(h[i][j][0]));
            h[i][j][1] = __float2half_rn(v.y);
            l[i][j][1] = __float2half_rn(v.y - __half2float(h[i][j][1]));
        }

#pragma unroll
    for (int i = 0; i < 2; i++) {
        int o = to * 2 + i;
#pragma unroll
        for (int j = 0; j < 2; j++) {
            size_t off = ((size_t)b * 32 + o) * NN + n0 + 4 * tp + 2 * j;
            *(__half2*)&QH[off] = __halves2half2(h[i][j][0], h[i][j][1]);
            *(__half2*)&QL[off] = __halves2half2(l[i][j][0], l[i][j][1]);
        }
    }
#pragma unroll
    for (int j = 0; j < 2; j++)
#pragma unroll
        for (int xy = 0; xy < 2; xy++) {
            int n = n0 + 4 * tp + 2 * j + xy;
            size_t off = ((size_t)b * NN + n) * 32 + to * 2;
            *(__half2*)&QTH[off] = __halves2half2(h[0][j][xy], h[1][j][xy]);
            *(__half2*)&QTL[off] = __halves2half2(l[0][j][xy], l[1][j][xy]);
        }
}

// ---------------- gemm_hmma: Y[b,o,n] = sum_c W[o,c]*(X1-X2)[b,c,n] + bias -----
__global__ __launch_bounds__(256, 2) void gemm_hmma(
    const float* __restrict__ W, const float* __restrict__ X1,
    const float* __restrict__ X2, const float* __restrict__ bias,
    float* __restrict__ Y, __half* __restrict__ Yh)
{
    __shared__ __half Wh[128][40];
    __shared__ __half Wl[128][40];
    __shared__ __half Xh[32][72];
    __shared__ __half Xl[32][72];
    __shared__ float  sS[128][2];
    __shared__ float  sQ[128][2];

    const int b  = blockIdx.y;
    const int nb = blockIdx.x;
    const int n0 = nb * 64;
    const int tid = threadIdx.x;
    const int wid = tid >> 5, lane = tid & 31;
    const int wc = wid & 3, wm = wid >> 2;

    const float* x1 = X1 + (size_t)b * CC * NN;
    const float* x2 = X2 ? X2 + (size_t)b * CC * NN : nullptr;

    float acc[2][4][4];
#pragma unroll
    for (int i = 0; i < 2; i++)
#pragma unroll
        for (int j = 0; j < 4; j++)
#pragma unroll
            for (int k = 0; k < 4; k++) acc[i][j][k] = 0.f;

    const int lrow = (lane & 7) + ((lane >> 3) & 1) * 8;
    const int lsel = lane >> 4;
    const int g = lane >> 3;

    for (int c0 = 0; c0 < CC; c0 += 32) {
#pragma unroll
        for (int u = 0; u < 2; u++) {
            int idx = tid + u * 256;
            int o = idx >> 2, kg = idx & 3;
            const float* wsrc = W + (size_t)o * CC + c0 + kg * 8;
            float4 w0 = *(const float4*)&wsrc[0];
            float4 w1 = *(const float4*)&wsrc[4];
            __half2 hh[4], ll[4];
            split2(w0.x, w0.y, hh[0], ll[0]);
            split2(w0.z, w0.w, hh[1], ll[1]);
            split2(w1.x, w1.y, hh[2], ll[2]);
            split2(w1.z, w1.w, hh[3], ll[3]);
            *(uint4*)&Wh[o][kg * 8] = *(const uint4*)&hh[0];
            *(uint4*)&Wl[o][kg * 8] = *(const uint4*)&ll[0];
        }
#pragma unroll
        for (int u = 0; u < 2; u++) {
            int idx = tid + u * 256;
            int r = idx >> 4, s = idx & 15;
            float4 v = *(const float4*)&x1[(size_t)(c0 + r) * NN + n0 + s * 4];
            if (x2) {
                float4 w = *(const float4*)&x2[(size_t)(c0 + r) * NN + n0 + s * 4];
                v.x -= w.x; v.y -= w.y; v.z -= w.z; v.w -= w.w;
            }
            __half2 hh[2], ll[2];
            split2(v.x, v.y, hh[0], ll[0]);
            split2(v.z, v.w, hh[1], ll[1]);
            *(uint2*)&Xh[r][s * 4] = *(const uint2*)&hh[0];
            *(uint2*)&Xl[r][s * 4] = *(const uint2*)&ll[0];
        }
        __syncthreads();

#pragma unroll
        for (int kk = 0; kk < 2; kk++) {
            unsigned ah[2][4], al[2][4];
#pragma unroll
            for (int ci = 0; ci < 2; ci++) {
                ldsm_x4(ah[ci][0], ah[ci][1], ah[ci][2], ah[ci][3],
                        &Wh[wc * 32 + ci * 16 + lrow][kk * 16 + lsel * 8]);
                ldsm_x4(al[ci][0], al[ci][1], al[ci][2], al[ci][3],
                        &Wl[wc * 32 + ci * 16 + lrow][kk * 16 + lsel * 8]);
            }
            unsigned bh[4][2], bl[4][2];
#pragma unroll
            for (int h = 0; h < 2; h++) {
                unsigned t0, t1, t2, t3;
                ldsm_x4_t(t0, t1, t2, t3,
                          &Xh[kk * 16 + (g & 1) * 8 + (lane & 7)][wm * 32 + h * 16 + (g >> 1) * 8]);
                bh[h * 2 + 0][0] = t0; bh[h * 2 + 0][1] = t1;
                bh[h * 2 + 1][0] = t2; bh[h * 2 + 1][1] = t3;
                ldsm_x4_t(t0, t1, t2, t3,
                          &Xl[kk * 16 + (g & 1) * 8 + (lane & 7)][wm * 32 + h * 16 + (g >> 1) * 8]);
                bl[h * 2 + 0][0] = t0; bl[h * 2 + 0][1] = t1;
                bl[h * 2 + 1][0] = t2; bl[h * 2 + 1][1] = t3;
            }
#pragma unroll
            for (int ci = 0; ci < 2; ci++)
#pragma unroll
                for (int nf = 0; nf < 4; nf++) {
                    mma16816(acc[ci][nf], ah[ci], bh[nf]);
                    mma16816(acc[ci][nf], ah[ci], bl[nf]);
                    mma16816(acc[ci][nf], al[ci], bh[nf]);
                }
        }
        __syncthreads();
    }

    const int r0l = lane >> 2, c0l = (lane & 3) * 2;
    float sv[2][2] = {{0.f, 0.f}, {0.f, 0.f}};
    float qv[2][2] = {{0.f, 0.f}, {0.f, 0.f}};

#pragma unroll
    for (int ci = 0; ci < 2; ci++) {
        int oLo = wc * 32 + ci * 16 + r0l;
        int oHi = oLo + 8;
        float biLo = bias ? bias[oLo] : 0.f;
        float biHi = bias ? bias[oHi] : 0.f;
#pragma unroll
        for (int nf = 0; nf < 4; nf++) {
            int mm = wm * 32 + nf * 8 + c0l;
            float2 v0 = make_float2(acc[ci][nf][0] + biLo, acc[ci][nf][1] + biLo);
            float2 v1 = make_float2(acc[ci][nf][2] + biHi, acc[ci][nf][3] + biHi);
            size_t offLo = ((size_t)b * CC + oLo) * NN + n0 + mm;
            size_t offHi = ((size_t)b * CC + oHi) * NN + n0 + mm;
            if (Yh) {
                *(__half2*)&Yh[offLo] = __floats2half2_rn(v0.x, v0.y);
                *(__half2*)&Yh[offHi] = __floats2half2_rn(v1.x, v1.y);
            } else {
                *(float2*)&Y[offLo] = v0;
                *(float2*)&Y[offHi] = v1;
                sv[ci][0] += v0.x + v0.y;
                qv[ci][0] += v0.x * v0.x + v0.y * v0.y;
                sv[ci][1] += v1.x + v1.y;
                qv[ci][1] += v1.x * v1.x + v1.y * v1.y;
            }
        }
    }

    if (!Yh) {
#pragma unroll
        for (int ci = 0; ci < 2; ci++)
#pragma unroll
            for (int h = 0; h < 2; h++) {
                float s = sv[ci][h], q = qv[ci][h];
                s += __shfl_xor_sync(0xffffffffu, s, 1);
                s += __shfl_xor_sync(0xffffffffu, s, 2);
                q += __shfl_xor_sync(0xffffffffu, q, 1);
                q += __shfl_xor_sync(0xffffffffu, q, 2);
                if ((lane & 3) == 0) {
                    int oo = wc * 32 + ci * 16 + h * 8 + r0l;
                    sS[oo][wm] = s;
                    sQ[oo][wm] = q;
                }
            }
        __syncthreads();
        if (tid < 128) {
            g_bnpS[nb][b][tid] = sS[tid][0] + sS[tid][1];
            g_bnpQ[nb][b][tid] = sQ[tid][0] + sQ[tid][1];
        }
    }
}

// ---------------- pass 1: energy + tile softmax STATS only (no U write) --------
__global__ __launch_bounds__(256, 2) void energy_stats(
    const __half* __restrict__ QH, const __half* __restrict__ QL,
    const __half* __restrict__ QTH, const __half* __restrict__ QTL,
    const int* __restrict__ mask)
{
    __shared__ __half Ah[64][40];
    __shared__ __half Al[64][40];
    __shared__ __half Bh[32][136];
    __shared__ __half Bl[32][136];
    __shared__ float  redu[64][4];
    __shared__ float  rowmax_s[64];
    __shared__ int    cms[128];
    __shared__ int    rms[64];

    const int b  = blockIdx.z;
    const int n0 = blockIdx.y * 64;
    const int m0 = blockIdx.x * 128;
    const int mt = blockIdx.x;
    const int tid = threadIdx.x;
    const int wid = tid >> 5, lane = tid & 31;
    const int wn = wid & 1, wm = wid >> 1;

    {
        int r = tid >> 2, s = tid & 3;
        size_t off = ((size_t)b * NN + n0 + r) * 32 + s * 8;
        *(uint4*)&Ah[r][s * 8] = *(const uint4*)&QTH[off];
        *(uint4*)&Al[r][s * 8] = *(const uint4*)&QTL[off];
    }
#pragma unroll
    for (int u = 0; u < 2; u++) {
        int idx = tid + u * 256;
        int r = idx >> 4, s = idx & 15;
        size_t off = ((size_t)b * 32 + r) * NN + m0 + s * 8;
        *(uint4*)&Bh[r][s * 8] = *(const uint4*)&QH[off];
        *(uint4*)&Bl[r][s * 8] = *(const uint4*)&QL[off];
    }
    if (tid < 128) cms[tid] = mask[(size_t)b * NN + m0 + tid];
    if (tid < 64)  rms[tid] = mask[(size_t)b * NN + n0 + tid];
    __syncthreads();

    float acc[2][4][4];
#pragma unroll
    for (int i = 0; i < 2; i++)
#pragma unroll
        for (int j = 0; j < 4; j++)
#pragma unroll
            for (int k = 0; k < 4; k++) acc[i][j][k] = 0.f;

    const int lrow = (lane & 7) + ((lane >> 3) & 1) * 8;
    const int lsel = lane >> 4;
    const int g = lane >> 3;
    const int r0l = lane >> 2, c0l = (lane & 3) * 2;

#pragma unroll
    for (int kk = 0; kk < 2; kk++) {
        unsigned ah[2][4], al[2][4];
#pragma unroll
        for (int ci = 0; ci < 2; ci++) {
            ldsm_x4(ah[ci][0], ah[ci][1], ah[ci][2], ah[ci][3],
                    &Ah[wn * 32 + ci * 16 + lrow][kk * 16 + lsel * 8]);
            ldsm_x4(al[ci][0], al[ci][1], al[ci][2], al[ci][3],
                    &Al[wn * 32 + ci * 16 + lrow][kk * 16 + lsel * 8]);
        }
        unsigned bh[4][2], bl[4][2];
#pragma unroll
        for (int h = 0; h < 2; h++) {
            unsigned t0, t1, t2, t3;
            ldsm_x4_t(t0, t1, t2, t3,
                      &Bh[kk * 16 + (g & 1) * 8 + (lane & 7)][wm * 32 + h * 16 + (g >> 1) * 8]);
            bh[h * 2 + 0][0] = t0; bh[h * 2 + 0][1] = t1;
            bh[h * 2 + 1][0] = t2; bh[h * 2 + 1][1] = t3;
            ldsm_x4_t(t0, t1, t2, t3,
                      &Bl[kk * 16 + (g & 1) * 8 + (lane & 7)][wm * 32 + h * 16 + (g >> 1) * 8]);
            bl[h * 2 + 0][0] = t0; bl[h * 2 + 0][1] = t1;
            bl[h * 2 + 1][0] = t2; bl[h * 2 + 1][1] = t3;
        }
#pragma unroll
        for (int ci = 0; ci < 2; ci++)
#pragma unroll
            for (int nf = 0; nf < 4; nf++) {
                mma16816(acc[ci][nf], ah[ci], bh[nf]);
                mma16816(acc[ci][nf], ah[ci], bl[nf]);
                mma16816(acc[ci][nf], al[ci], bh[nf]);
            }
    }

    float vmax[2][2];
    vmax[0][0] = NEGV; vmax[0][1] = NEGV; vmax[1][0] = NEGV; vmax[1][1] = NEGV;
#pragma unroll
    for (int ci = 0; ci < 2; ci++)
#pragma unroll
        for (int nf = 0; nf < 4; nf++) {
            int mm = wm * 32 + nf * 8 + c0l;
            int cm0 = cms[mm], cm1 = cms[mm + 1];
#pragma unroll
            for (int h = 0; h < 2; h++) {
                int rm = rms[wn * 32 + ci * 16 + h * 8 + r0l];
                float v0 = (rm && cm0) ? acc[ci][nf][h * 2 + 0] : NEGV;
                float v1 = (rm && cm1) ? acc[ci][nf][h * 2 + 1] : NEGV;
                acc[ci][nf][h * 2 + 0] = v0;
                acc[ci][nf][h * 2 + 1] = v1;
                vmax[ci][h] = fmaxf(vmax[ci][h], fmaxf(v0, v1));
            }
        }
#pragma unroll
    for (int ci = 0; ci < 2; ci++)
#pragma unroll
        for (int h = 0; h < 2; h++) {
            float v = vmax[ci][h];
            v = fmaxf(v, __shfl_xor_sync(0xffffffffu, v, 1));
            v = fmaxf(v, __shfl_xor_sync(0xffffffffu, v, 2));
            vmax[ci][h] = v;
        }
    if ((lane & 3) == 0) {
#pragma unroll
        for (int ci = 0; ci < 2; ci++)
#pragma unroll
            for (int h = 0; h < 2; h++)
                redu[wn * 32 + ci * 16 + h * 8 + r0l][wm] = vmax[ci][h];
    }
    __syncthreads();
    if (tid < 64) {
        float v = fmaxf(fmaxf(redu[tid][0], redu[tid][1]),
                        fmaxf(redu[tid][2], redu[tid][3]));
        rowmax_s[tid] = v;
        g_tmax[((size_t)mt * BB + b) * NN + n0 + tid] = v;
    }
    __syncthreads();

    float mx_[2][2];
#pragma unroll
    for (int ci = 0; ci < 2; ci++)
#pragma unroll
        for (int h = 0; h < 2; h++)
            mx_[ci][h] = rowmax_s[wn * 32 + ci * 16 + h * 8 + r0l];

    float rsum[2][2] = {{0.f, 0.f}, {0.f, 0.f}};
#pragma unroll
    for (int ci = 0; ci < 2; ci++)
#pragma unroll
        for (int nf = 0; nf < 4; nf++) {
#pragma unroll
            for (int h = 0; h < 2; h++) {
                float x0 = (acc[ci][nf][h * 2 + 0] - mx_[ci][h]) * LOG2E;
                float x1 = (acc[ci][nf][h * 2 + 1] - mx_[ci][h]) * LOG2E;
                __half2 u2 = h2_ex2(__floats2half2_rn(x0, x1));
                float2 uf = __half22float2(u2);
                rsum[ci][h] += uf.x + uf.y;
            }
        }
#pragma unroll
    for (int ci = 0; ci < 2; ci++)
#pragma unroll
        for (int h = 0; h < 2; h++) {
            float v = rsum[ci][h];
            v += __shfl_xor_sync(0xffffffffu, v, 1);
            v += __shfl_xor_sync(0xffffffffu, v, 2);
            rsum[ci][h] = v;
        }
    if ((lane & 3) == 0) {
#pragma unroll
        for (int ci = 0; ci < 2; ci++)
#pragma unroll
            for (int h = 0; h < 2; h++)
                redu[wn * 32 + ci * 16 + h * 8 + r0l][wm] = rsum[ci][h];
    }
    __syncthreads();
    if (tid < 64) {
        float s = (redu[tid][0] + redu[tid][1]) + (redu[tid][2] + redu[tid][3]);
        g_tsum[((size_t)mt * BB + b) * NN + n0 + tid] = s;
    }
}

// ---------------- rowscale: global rm[n] and fs[n] = FSCALE/rowsum -------------
__global__ __launch_bounds__(256) void rowscale_kernel()
{
    const int b = blockIdx.y;
    const int n = blockIdx.x * 256 + threadIdx.x;
    float mx[32];
    float m_row;
#pragma unroll
    for (int t = 0; t < 32; t++) {
        mx[t] = g_tmax[((size_t)t * BB + b) * NN + n];
        m_row = (t == 0) ? mx[0] : fmaxf(m_row, mx[t]);
    }
    float s = 0.f;
#pragma unroll
    for (int t = 0; t < 32; t++)
        s += __expf(mx[t] - m_row) * g_tsum[((size_t)t * BB + b) * NN + n];
    g_rm[(size_t)b * NN + n] = m_row;
    g_fs[(size_t)b * NN + n] = FSCALE / s;
}

// ---------------- apply_fused: recompute energy, exp, XV MMA, colnorm ----------
// grid (NN/64 m-tiles, BB), 256 threads = 8 warps.
// Energy warps: (wc 4 x 16n) x (wm 2 x 32m). Main MMA warps: (wc 4 x 32c) x (wm 2 x 32m).
__global__ __launch_bounds__(256, 2) void apply_fused(
    const __half* __restrict__ XVH,
    const __half* __restrict__ QH, const __half* __restrict__ QL,
    const __half* __restrict__ QTH, const __half* __restrict__ QTL,
    const int* __restrict__ mask, float* __restrict__ XR)
{
    __shared__ __align__(16) char sraw[48384];
    __half (*XVs)[72] = (__half(*)[72])(sraw);                  // 18432
    __half (*Bmh)[72] = (__half(*)[72])(sraw + 18432);          // 4608
    __half (*Bml)[72] = (__half(*)[72])(sraw + 23040);          // 4608
    __half (*Anh)[40] = (__half(*)[40])(sraw + 27648);          // 5120
    __half (*Anl)[40] = (__half(*)[40])(sraw + 32768);          // 5120
    __half (*As)[72]  = (__half(*)[72])(sraw + 37888);          // 9216
    float* rmS = (float*)(sraw + 47104);                        // 256
    float* fsS = (float*)(sraw + 47360);                        // 256
    int*   mkS = (int*)(sraw + 47616);                          // 256
    int*   cmS = (int*)(sraw + 47872);                          // 256
    // epilogue aliases (used after final sync, XVs dead):
    float (*cs_s)[68] = (float(*)[68])(sraw);                   // 8704
    float* cinv_s = (float*)(sraw + 8704);                      // 256

    const int b  = blockIdx.y;
    const int m0 = blockIdx.x * 64;
    const int tid = threadIdx.x;
    const int wid = tid >> 5, lane = tid & 31;
    const int wc = wid & 3, wm = wid >> 2;

    const __half* xv = XVH + (size_t)b * CC * NN;
    const float*  rm_g = g_rm + (size_t)b * NN;
    const float*  fs_g = g_fs + (size_t)b * NN;
    const int*    mk_g = mask + (size_t)b * NN;

    const int lrow = (lane & 7) + ((lane >> 3) & 1) * 8;
    const int lsel = lane >> 4;
    const int g = lane >> 3;
    const int r0l = lane >> 2, c0l = (lane & 3) * 2;

    // B operand (fixed): Q[o 0..31][m0..m0+63] hi/lo
    {
        int r = tid >> 3, s = tid & 7;
        size_t off = ((size_t)b * 32 + r) * NN + m0 + s * 8;
        *(uint4*)&Bmh[r][s * 8] = *(const uint4*)&QH[off];
        *(uint4*)&Bml[r][s * 8] = *(const uint4*)&QL[off];
    }
    if (tid < 64) cmS[tid] = mk_g[m0 + tid];

    float acc[2][4][4];
#pragma unroll
    for (int i = 0; i < 2; i++)
#pragma unroll
        for (int j = 0; j < 4; j++)
#pragma unroll
            for (int k = 0; k < 4; k++) acc[i][j][k] = 0.f;

    float2 cs2[4];
#pragma unroll
    for (int j = 0; j < 4; j++) cs2[j] = make_float2(0.f, 0.f);

    for (int k0 = 0; k0 < NN; k0 += 64) {
        __syncthreads();   // prev main MMA done; Bm ready on first iter after its fill
        // fills: XV (L2), An = QT rows k0..k0+63 (L2), row stats
#pragma unroll
        for (int u = 0; u < 4; u++) {
            int idx = tid + u * 256;
            int r = idx >> 3, s = idx & 7;
            *(uint4*)&XVs[r][s * 8] = *(const uint4*)&xv[(size_t)r * NN + k0 + s * 8];
        }
        {
            int r = tid >> 2, s = tid & 3;
            size_t off = ((size_t)b * NN + k0 + r) * 32 + s * 8;
            *(uint4*)&Anh[r][s * 8] = *(const uint4*)&QTH[off];
            *(uint4*)&Anl[r][s * 8] = *(const uint4*)&QTL[off];
        }
        if (tid < 64) {
            rmS[tid] = rm_g[k0 + tid];
            fsS[tid] = fs_g[k0 + tid];
            mkS[tid] = mk_g[k0 + tid];
        }
        __syncthreads();

        // energy MMA: E[64n x 64m], per warp 16n x 32m
        float acc_e[4][4];
#pragma unroll
        for (int j = 0; j < 4; j++)
#pragma unroll
            for (int k = 0; k < 4; k++) acc_e[j][k] = 0.f;

#pragma unroll
        for (int kk = 0; kk < 2; kk++) {
            unsigned aeh[4], ael[4];
            ldsm_x4(aeh[0], aeh[1], aeh[2], aeh[3],
                    &Anh[wc * 16 + lrow][kk * 16 + lsel * 8]);
            ldsm_x4(ael[0], ael[1], ael[2], ael[3],
                    &Anl[wc * 16 + lrow][kk * 16 + lsel * 8]);
            unsigned beh[4][2], bel[4][2];
#pragma unroll
            for (int h = 0; h < 2; h++) {
                unsigned t0, t1, t2, t3;
                ldsm_x4_t(t0, t1, t2, t3,
                          &Bmh[kk * 16 + (g & 1) * 8 + (lane & 7)][wm * 32 + h * 16 + (g >> 1) * 8]);
                beh[h * 2 + 0][0] = t0; beh[h * 2 + 0][1] = t1;
                beh[h * 2 + 1][0] = t2; beh[h * 2 + 1][1] = t3;
                ldsm_x4_t(t0, t1, t2, t3,
                          &Bml[kk * 16 + (g & 1) * 8 + (lane & 7)][wm * 32 + h * 16 + (g >> 1) * 8]);
                bel[h * 2 + 0][0] = t0; bel[h * 2 + 0][1] = t1;
                bel[h * 2 + 1][0] = t2; bel[h * 2 + 1][1] = t3;
            }
#pragma unroll
            for (int nf = 0; nf < 4; nf++) {
                mma16816(acc_e[nf], aeh, beh[nf]);
                mma16816(acc_e[nf], aeh, bel[nf]);
                mma16816(acc_e[nf], ael, beh[nf]);
            }
        }

        // exp transform -> As
#pragma unroll
        for (int h = 0; h < 2; h++) {
            int nl = wc * 16 + h * 8 + r0l;
            int rmk = mkS[nl];
            float rm = rmS[nl];
            __half2 fs2 = __half2half2(__float2half_rn(fsS[nl]));
#pragma unroll
            for (int nf = 0; nf < 4; nf++) {
                int mmE = wm * 32 + nf * 8 + c0l;
                int cm0 = cmS[mmE], cm1 = cmS[mmE + 1];
                float e0 = acc_e[nf][h * 2 + 0];
                float e1 = acc_e[nf][h * 2 + 1];
                float x0 = rmk ? (cm0 ? (e0 - rm) * LOG2E : -60000.f) : 0.f;
                float x1 = rmk ? (cm1 ? (e1 - rm) * LOG2E : -60000.f) : 0.f;
                __half2 a2 = __hmul2(h2_ex2(__floats2half2_rn(x0, x1)), fs2);
                *(__half2*)&As[nl][mmE] = a2;
                float2 af = __half22float2(a2);
                cs2[nf].x += af.x; cs2[nf].y += af.y;
            }
        }
        __syncthreads();

        // main MMA: XR += XVs @ As
#pragma unroll
        for (int kk = 0; kk < 4; kk++) {
            unsigned a[2][4];
#pragma unroll
            for (int ci = 0; ci < 2; ci++)
                ldsm_x4(a[ci][0], a[ci][1], a[ci][2], a[ci][3],
                        &XVs[wc * 32 + ci * 16 + lrow][kk * 16 + lsel * 8]);
            unsigned bf[4][2];
#pragma unroll
            for (int h = 0; h < 2; h++) {
                unsigned t0, t1, t2, t3;
                ldsm_x4_t(t0, t1, t2, t3,
                          &As[kk * 16 + (g & 1) * 8 + (lane & 7)][wm * 32 + h * 16 + (g >> 1) * 8]);
                bf[h * 2 + 0][0] = t0; bf[h * 2 + 0][1] = t1;
                bf[h * 2 + 1][0] = t2; bf[h * 2 + 1][1] = t3;
            }
#pragma unroll
            for (int ci = 0; ci < 2; ci++)
#pragma unroll
                for (int nf = 0; nf < 4; nf++)
                    mma16816(acc[ci][nf], a[ci], bf[nf]);
        }
    }
    __syncthreads();

    // column sums -> colinv. Writers of column set wm: warps wid&3, lanes r0l.
    {
        int gg = (wid & 3) * 8 + r0l;
#pragma unroll
        for (int nf = 0; nf < 4; nf++) {
            int mmE = wm * 32 + nf * 8 + c0l;
            cs_s[gg][mmE]     = cs2[nf].x;
            cs_s[gg][mmE + 1] = cs2[nf].y;
        }
    }
    __syncthreads();
    if (tid < 64) {
        float tot = 0.f;
#pragma unroll
        for (int gg = 0; gg < 32; gg++) tot += cs_s[gg][tid];
        cinv_s[tid] = 1.f / (1e-9f + tot);
    }
    __syncthreads();

#pragma unroll
    for (int ci = 0; ci < 2; ci++) {
#pragma unroll
        for (int nf = 0; nf < 4; nf++) {
            int c = wc * 32 + ci * 16 + r0l;
            int mm = wm * 32 + nf * 8 + c0l;
            float2 cv = *(const float2*)&cinv_s[mm];
            float2 lo = make_float2(acc[ci][nf][0] * cv.x, acc[ci][nf][1] * cv.y);
            *(float2*)&XR[((size_t)b * CC + c) * NN + m0 + mm] = lo;
            float2 hi = make_float2(acc[ci][nf][2] * cv.x, acc[ci][nf][3] * cv.y);
            *(float2*)&XR[((size_t)b * CC + c + 8) * NN + m0 + mm] = hi;
        }
    }
}

// ---------------- BN finalize from gemm partials --------------------------------
__global__ void bn_finalize_kernel(const float* __restrict__ gam, const float* __restrict__ bet)
{
    const int c = threadIdx.x;
    float ts = 0.f, t2 = 0.f;
    for (int i = 0; i < 64; i++)
#pragma unroll
        for (int b = 0; b < BB; b++) {
            ts += g_bnpS[i][b][c];
            t2 += g_bnpQ[i][b][c];
        }
    const float invN = 1.f / (float)(BB * NN);
    float mean = ts * invN;
    float var  = t2 * invN - mean * mean;
    float sc = gam[c] * rsqrtf(var + 1e-5f);
    g_scale[c] = sc;
    g_shift[c] = bet[c] - mean * sc;
}

// ---------------- BN apply (+relu) [+residual into h and output slab] -----------
__global__ __launch_bounds__(256) void bn_apply_kernel(
    const float* __restrict__ Y, float* __restrict__ H,
    float* __restrict__ OUT, int layer)
{
    size_t f = ((size_t)blockIdx.x * 256 + threadIdx.x) * 4;
    int n = (int)(f % NN);
    int c = (int)((f / NN) % CC);
    int b = (int)(f / ((size_t)NN * CC));
    float sc = g_scale[c], sh = g_shift[c];
    float4 y = *(const float4*)&Y[f];
    float4 r;
    r.x = fmaxf(fmaf(y.x, sc, sh), 0.f);
    r.y = fmaxf(fmaf(y.y, sc, sh), 0.f);
    r.z = fmaxf(fmaf(y.z, sc, sh), 0.f);
    r.w = fmaxf(fmaf(y.w, sc, sh), 0.f);
    if (OUT) {
        float4 h = *(const float4*)&H[f];
        r.x += h.x; r.y += h.y; r.z += h.z; r.w += h.w;
        *(float4*)&H[f] = r;
        *(float4*)&OUT[(((size_t)b * 4 * CC) + (size_t)layer * CC + c) * NN + n] = r;
    } else {
        *(float4*)&H[f] = r;
    }
}

// ---------------- launch ---------------------------------------------------------
extern "C" void kernel_launch(void* const* d_in, const int* in_sizes, int n_in,
                              void* d_out, int out_size)
{
    const float* x    = (const float*)d_in[0];
    const int*   mask = (const int*)  d_in[1];
    const float* w1   = (const float*)d_in[2];
    const float* g1   = (const float*)d_in[3];
    const float* b1   = (const float*)d_in[4];
    const float* w2   = (const float*)d_in[5];
    const float* g2   = (const float*)d_in[6];
    const float* b2   = (const float*)d_in[7];
    const float* wqk  = (const float*)d_in[8];
    const float* wv   = (const float*)d_in[9];
    const float* bv   = (const float*)d_in[10];
    const float* wt   = (const float*)d_in[11];
    const float* bt   = (const float*)d_in[12];
    const float* sg   = (const float*)d_in[13];
    const float* sb   = (const float*)d_in[14];
    float* out = (float*)d_out;

    float *p_h, *p_y, *p_xr;
    __half *p_xvh, *p_qh, *p_ql, *p_qth, *p_qtl;
    cudaGetSymbolAddress((void**)&p_h,   g_h);
    cudaGetSymbolAddress((void**)&p_y,   g_y);
    cudaGetSymbolAddress((void**)&p_xvh, g_xvh);
    cudaGetSymbolAddress((void**)&p_xr,  g_xr);
    cudaGetSymbolAddress((void**)&p_qh,  g_qh);
    cudaGetSymbolAddress((void**)&p_ql,  g_ql);
    cudaGetSymbolAddress((void**)&p_qth, g_qth);
    cudaGetSymbolAddress((void**)&p_qtl, g_qtl);

    const dim3 blk256(256);
    const dim3 grid_gh(NN / 64, BB);
    const dim3 grid_qk(NN / 64, 1, BB);
    const dim3 grid_es(NN / 128, NN / 64, BB);
    const dim3 grid_rs(NN / 256, BB);
    const dim3 grid_ap(NN / 64, BB);
    const dim3 grid_ba((unsigned)(((size_t)BB * CC * NN / 4) / 256));

    // head: two conv+BN+relu
    gemm_hmma<<<grid_gh, blk256>>>(w1, x, nullptr, nullptr, p_y, nullptr);
    bn_finalize_kernel<<<1, CC>>>(g1, b1);
    bn_apply_kernel<<<grid_ba, blk256>>>(p_y, p_h, nullptr, 0);

    gemm_hmma<<<grid_gh, blk256>>>(w2, p_h, nullptr, nullptr, p_y, nullptr);
    bn_finalize_kernel<<<1, CC>>>(g2, b2);
    bn_apply_kernel<<<grid_ba, blk256>>>(p_y, p_h, nullptr, 0);

    // 4 offset-attention layers
    for (int i = 0; i < 4; i++) {
        gemm_qk<<<grid_qk, blk256>>>(wqk + (size_t)i * 32 * CC, p_h, p_qh, p_ql, p_qth, p_qtl);
        energy_stats<<<grid_es, blk256>>>(p_qh, p_ql, p_qth, p_qtl, mask);
        rowscale_kernel<<<grid_rs, blk256>>>();
        gemm_hmma<<<grid_gh, blk256>>>(wv + (size_t)i * CC * CC, p_h, nullptr, bv + (size_t)i * CC,
                                       nullptr, p_xvh);
        apply_fused<<<grid_ap, blk256>>>(p_xvh, p_qh, p_ql, p_qth, p_qtl, mask, p_xr);
        gemm_hmma<<<grid_gh, blk256>>>(wt + (size_t)i * CC * CC, p_h, p_xr, bt + (size_t)i * CC,
                                       p_y, nullptr);
        bn_finalize_kernel<<<1, CC>>>(sg + (size_t)i * CC, sb + (size_t)i * CC);
        bn_apply_kernel<<<grid_ba, blk256>>>(p_y, p_h, out, i);
    }
}

// round 14
// speedup vs baseline: 1.1821x; 1.1821x over previous
#include <cuda_runtime.h>
#include <cuda_fp16.h>
#include <cstdint>
#include <cstddef>

#define NN 4096
#define CC 128
#define BB 4
#define NEGV (-9e15f)
#define LOG2E 1.4426950408889634f
#define FSCALE 256.0f

typedef unsigned long long ull;

// ---------------- scratch (device globals: no allocation allowed) -----------
__device__ float  g_h[(size_t)BB * CC * NN];                 // 8 MB
__device__ float  g_y[(size_t)BB * CC * NN];                 // 8 MB
__device__ __half g_qh[(size_t)BB * 32 * NN];                // 1 MB
__device__ __half g_ql[(size_t)BB * 32 * NN];                // 1 MB
__device__ __half g_qth[(size_t)BB * NN * 32];               // 1 MB
__device__ __half g_qtl[(size_t)BB * NN * 32];               // 1 MB
__device__ __half g_xvh[(size_t)BB * CC * NN];               // 4 MB
__device__ float  g_xr[(size_t)BB * CC * NN];                // 8 MB
__device__ __half g_u[(size_t)BB * NN * NN];                 // 128 MB
__device__ float  g_tmax[(size_t)32 * BB * NN];
__device__ float  g_tsum[(size_t)32 * BB * NN];
__device__ __half g_rowscale[(size_t)32 * BB * NN];
__device__ float  g_scale[CC];
__device__ float  g_shift[CC];
__device__ float  g_bnpS[64][BB][CC];
__device__ float  g_bnpQ[64][BB][CC];

// ---------------- helpers ----------------------------------------------------
__device__ __forceinline__ void fma2(ull& acc, ull a, ull b) {
    asm("fma.rn.f32x2 %0, %1, %2, %0;" : "+l"(acc) : "l"(a), "l"(b));
}
__device__ __forceinline__ ull pack2(float v) {
    ull r;
    unsigned u = __float_as_uint(v);
    asm("mov.b64 %0, {%1, %1};" : "=l"(r) : "r"(u));
    return r;
}
__device__ __forceinline__ float2 unpack2(ull v) {
    unsigned lo, hi;
    asm("mov.b64 {%0, %1}, %2;" : "=r"(lo), "=r"(hi) : "l"(v));
    return make_float2(__uint_as_float(lo), __uint_as_float(hi));
}
__device__ __forceinline__ __half2 h2_ex2(__half2 x) {
    unsigned xi = *(unsigned*)&x;
    unsigned ri;
    asm("ex2.approx.f16x2 %0, %1;" : "=r"(ri) : "r"(xi));
    return *(__half2*)&ri;
}
__device__ __forceinline__ void split2(float a, float b, __half2& h, __half2& l) {
    __half ha = __float2half_rn(a), hb = __float2half_rn(b);
    __half la = __float2half_rn(a - __half2float(ha));
    __half lb = __float2half_rn(b - __half2float(hb));
    h = __halves2half2(ha, hb);
    l = __halves2half2(la, lb);
}

// ---------------- HMMA helpers -------------------------------------------------
__device__ __forceinline__ void ldsm_x4(unsigned& r0, unsigned& r1, unsigned& r2, unsigned& r3,
                                        const void* p) {
    unsigned addr = (unsigned)__cvta_generic_to_shared(p);
    asm volatile("ldmatrix.sync.aligned.m8n8.x4.shared.b16 {%0,%1,%2,%3}, [%4];"
        : "=r"(r0), "=r"(r1), "=r"(r2), "=r"(r3) : "r"(addr));
}
__device__ __forceinline__ void ldsm_x4_t(unsigned& r0, unsigned& r1, unsigned& r2, unsigned& r3,
                                          const void* p) {
    unsigned addr = (unsigned)__cvta_generic_to_shared(p);
    asm volatile("ldmatrix.sync.aligned.m8n8.x4.trans.shared.b16 {%0,%1,%2,%3}, [%4];"
        : "=r"(r0), "=r"(r1), "=r"(r2), "=r"(r3) : "r"(addr));
}
__device__ __forceinline__ void mma16816(float d[4], const unsigned a[4], const unsigned b[2]) {
    asm volatile("mma.sync.aligned.m16n8k16.row.col.f32.f16.f16.f32 "
        "{%0,%1,%2,%3}, {%4,%5,%6,%7}, {%8,%9}, {%0,%1,%2,%3};"
        : "+f"(d[0]), "+f"(d[1]), "+f"(d[2]), "+f"(d[3])
        : "r"(a[0]), "r"(a[1]), "r"(a[2]), "r"(a[3]), "r"(b[0]), "r"(b[1]));
}

// ---------------- gemm_qk: q = Wqk (32xC) * X; FMA2; fp16 hi/lo + transposed ---
__global__ __launch_bounds__(256, 3) void gemm_qk(
    const float* __restrict__ W, const float* __restrict__ X,
    __half* __restrict__ QH, __half* __restrict__ QL,
    __half* __restrict__ QTH, __half* __restrict__ QTL)
{
    __shared__ float Ws[CC][36];
    __shared__ __align__(16) double Xd[64][34];

    const int b  = blockIdx.z;
    const int n0 = blockIdx.x * 64;
    const int tid = threadIdx.x;
    const int to = tid >> 4;
    const int tp = tid & 15;

    for (int idx = tid; idx < 32 * CC; idx += 256) {
        int o = idx / CC, c = idx % CC;
        Ws[c][o] = W[(size_t)o * CC + c];
    }

    const float* x1 = X + (size_t)b * CC * NN;

    ull acc[2][2];
    acc[0][0] = acc[0][1] = acc[1][0] = acc[1][1] = 0ull;

    for (int c0 = 0; c0 < CC; c0 += 64) {
        __syncthreads();
#pragma unroll
        for (int t = 0; t < 4; t++) {
            int idx = tid + t * 256;
            int c = idx >> 4, q = idx & 15;
            float4 v = *(const float4*)&x1[(size_t)(c0 + c) * NN + n0 + q * 4];
            *(double2*)&Xd[c][q * 2] = *(const double2*)&v;
        }
        __syncthreads();
#pragma unroll 8
        for (int k = 0; k < 64; k++) {
            float2 w2 = *(const float2*)&Ws[c0 + k][to * 2];
            ull xc0 = pack2(w2.x), xc1 = pack2(w2.y);
            double2 ad = *(const double2*)&Xd[k][2 * tp];
            ull a0 = *(const ull*)&ad.x;
            ull a1 = *(const ull*)&ad.y;
            fma2(acc[0][0], xc0, a0); fma2(acc[0][1], xc0, a1);
            fma2(acc[1][0], xc1, a0); fma2(acc[1][1], xc1, a1);
        }
    }

    __half h[2][2][2], l[2][2][2];
#pragma unroll
    for (int i = 0; i < 2; i++)
#pragma unroll
        for (int j = 0; j < 2; j++) {
            float2 v = unpack2(acc[i][j]);
            h[i][j][0] = __float2half_rn(v.x);
            l[i][j][0] = __float2half_rn(v.x - __half2float(h[i][j][0]));
            h[i][j][1] = __float2half_rn(v.y);
            l[i][j][1] = __float2half_rn(v.y - __half2float(h[i][j][1]));
        }

#pragma unroll
    for (int i = 0; i < 2; i++) {
        int o = to * 2 + i;
#pragma unroll
        for (int j = 0; j < 2; j++) {
            size_t off = ((size_t)b * 32 + o) * NN + n0 + 4 * tp + 2 * j;
            *(__half2*)&QH[off] = __halves2half2(h[i][j][0], h[i][j][1]);
            *(__half2*)&QL[off] = __halves2half2(l[i][j][0], l[i][j][1]);
        }
    }
#pragma unroll
    for (int j = 0; j < 2; j++)
#pragma unroll
        for (int xy = 0; xy < 2; xy++) {
            int n = n0 + 4 * tp + 2 * j + xy;
            size_t off = ((size_t)b * NN + n) * 32 + to * 2;
            *(__half2*)&QTH[off] = __halves2half2(h[0][j][xy], h[1][j][xy]);
            *(__half2*)&QTL[off] = __halves2half2(l[0][j][xy], l[1][j][xy]);
        }
}

// ---------------- gemm_hmma: Y[b,o,n] = sum_c W[o,c]*(X1-X2)[b,c,n] + bias -----
// Register-prefetched X loads (chunk i+1's raw floats load during chunk i MMAs).
__global__ __launch_bounds__(256, 2) void gemm_hmma(
    const float* __restrict__ W, const float* __restrict__ X1,
    const float* __restrict__ X2, const float* __restrict__ bias,
    float* __restrict__ Y, __half* __restrict__ Yh)
{
    __shared__ __half Wh[128][40];
    __shared__ __half Wl[128][40];
    __shared__ __half Xh[32][72];
    __shared__ __half Xl[32][72];
    __shared__ float  sS[128][2];
    __shared__ float  sQ[128][2];

    const int b  = blockIdx.y;
    const int nb = blockIdx.x;
    const int n0 = nb * 64;
    const int tid = threadIdx.x;
    const int wid = tid >> 5, lane = tid & 31;
    const int wc = wid & 3, wm = wid >> 2;

    const float* x1 = X1 + (size_t)b * CC * NN;
    const float* x2 = X2 ? X2 + (size_t)b * CC * NN : nullptr;

    float acc[2][4][4];
#pragma unroll
    for (int i = 0; i < 2; i++)
#pragma unroll
        for (int j = 0; j < 4; j++)
#pragma unroll
            for (int k = 0; k < 4; k++) acc[i][j][k] = 0.f;

    const int lrow = (lane & 7) + ((lane >> 3) & 1) * 8;
    const int lsel = lane >> 4;
    const int g = lane >> 3;

    // per-thread X-fill coordinates (fixed across chunks)
    const int xr0 = tid >> 4,         xs0 = tid & 15;
    const int xr1 = (tid + 256) >> 4, xs1 = (tid + 256) & 15;

    // prologue: prefetch chunk 0's raw X
    float4 pv0 = *(const float4*)&x1[(size_t)xr0 * NN + n0 + xs0 * 4];
    float4 pv1 = *(const float4*)&x1[(size_t)xr1 * NN + n0 + xs1 * 4];
    float4 pw0, pw1;
    if (x2) {
        pw0 = *(const float4*)&x2[(size_t)xr0 * NN + n0 + xs0 * 4];
        pw1 = *(const float4*)&x2[(size_t)xr1 * NN + n0 + xs1 * 4];
    }

    for (int c0 = 0; c0 < CC; c0 += 32) {
        if (c0) __syncthreads();      // prior MMA done reading smem

        // W fill (L2-resident)
#pragma unroll
        for (int u = 0; u < 2; u++) {
            int idx = tid + u * 256;
            int o = idx >> 2, kg = idx & 3;
            const float* wsrc = W + (size_t)o * CC + c0 + kg * 8;
            float4 w0 = *(const float4*)&wsrc[0];
            float4 w1 = *(const float4*)&wsrc[4];
            __half2 hh[4], ll[4];
            split2(w0.x, w0.y, hh[0], ll[0]);
            split2(w0.z, w0.w, hh[1], ll[1]);
            split2(w1.x, w1.y, hh[2], ll[2]);
            split2(w1.z, w1.w, hh[3], ll[3]);
            *(uint4*)&Wh[o][kg * 8] = *(const uint4*)&hh[0];
            *(uint4*)&Wl[o][kg * 8] = *(const uint4*)&ll[0];
        }

        // X transform from prefetched registers
        {
            float4 v = pv0;
            if (x2) { v.x -= pw0.x; v.y -= pw0.y; v.z -= pw0.z; v.w -= pw0.w; }
            __half2 hh[2], ll[2];
            split2(v.x, v.y, hh[0], ll[0]);
            split2(v.z, v.w, hh[1], ll[1]);
            *(uint2*)&Xh[xr0][xs0 * 4] = *(const uint2*)&hh[0];
            *(uint2*)&Xl[xr0][xs0 * 4] = *(const uint2*)&ll[0];
        }
        {
            float4 v = pv1;
            if (x2) { v.x -= pw1.x; v.y -= pw1.y; v.z -= pw1.z; v.w -= pw1.w; }
            __half2 hh[2], ll[2];
            split2(v.x, v.y, hh[0], ll[0]);
            split2(v.z, v.w, hh[1], ll[1]);
            *(uint2*)&Xh[xr1][xs1 * 4] = *(const uint2*)&hh[0];
            *(uint2*)&Xl[xr1][xs1 * 4] = *(const uint2*)&ll[0];
        }

        // prefetch next chunk (overlaps with MMAs below)
        if (c0 + 32 < CC) {
            int cn = c0 + 32;
            pv0 = *(const float4*)&x1[(size_t)(cn + xr0) * NN + n0 + xs0 * 4];
            pv1 = *(const float4*)&x1[(size_t)(cn + xr1) * NN + n0 + xs1 * 4];
            if (x2) {
                pw0 = *(const float4*)&x2[(size_t)(cn + xr0) * NN + n0 + xs0 * 4];
                pw1 = *(const float4*)&x2[(size_t)(cn + xr1) * NN + n0 + xs1 * 4];
            }
        }
        __syncthreads();

#pragma unroll
        for (int kk = 0; kk < 2; kk++) {
            unsigned ah[2][4], al[2][4];
#pragma unroll
            for (int ci = 0; ci < 2; ci++) {
                ldsm_x4(ah[ci][0], ah[ci][1], ah[ci][2], ah[ci][3],
                        &Wh[wc * 32 + ci * 16 + lrow][kk * 16 + lsel * 8]);
                ldsm_x4(al[ci][0], al[ci][1], al[ci][2], al[ci][3],
                        &Wl[wc * 32 + ci * 16 + lrow][kk * 16 + lsel * 8]);
            }
            unsigned bh[4][2], bl[4][2];
#pragma unroll
            for (int h = 0; h < 2; h++) {
                unsigned t0, t1, t2, t3;
                ldsm_x4_t(t0, t1, t2, t3,
                          &Xh[kk * 16 + (g & 1) * 8 + (lane & 7)][wm * 32 + h * 16 + (g >> 1) * 8]);
                bh[h * 2 + 0][0] = t0; bh[h * 2 + 0][1] = t1;
                bh[h * 2 + 1][0] = t2; bh[h * 2 + 1][1] = t3;
                ldsm_x4_t(t0, t1, t2, t3,
                          &Xl[kk * 16 + (g & 1) * 8 + (lane & 7)][wm * 32 + h * 16 + (g >> 1) * 8]);
                bl[h * 2 + 0][0] = t0; bl[h * 2 + 0][1] = t1;
                bl[h * 2 + 1][0] = t2; bl[h * 2 + 1][1] = t3;
            }
#pragma unroll
            for (int ci = 0; ci < 2; ci++)
#pragma unroll
                for (int nf = 0; nf < 4; nf++) {
                    mma16816(acc[ci][nf], ah[ci], bh[nf]);
                    mma16816(acc[ci][nf], ah[ci], bl[nf]);
                    mma16816(acc[ci][nf], al[ci], bh[nf]);
                }
        }
    }
    __syncthreads();

    const int r0l = lane >> 2, c0l = (lane & 3) * 2;
    float sv[2][2] = {{0.f, 0.f}, {0.f, 0.f}};
    float qv[2][2] = {{0.f, 0.f}, {0.f, 0.f}};

#pragma unroll
    for (int ci = 0; ci < 2; ci++) {
        int oLo = wc * 32 + ci * 16 + r0l;
        int oHi = oLo + 8;
        float biLo = bias ? bias[oLo] : 0.f;
        float biHi = bias ? bias[oHi] : 0.f;
#pragma unroll
        for (int nf = 0; nf < 4; nf++) {
            int mm = wm * 32 + nf * 8 + c0l;
            float2 v0 = make_float2(acc[ci][nf][0] + biLo, acc[ci][nf][1] + biLo);
            float2 v1 = make_float2(acc[ci][nf][2] + biHi, acc[ci][nf][3] + biHi);
            size_t offLo = ((size_t)b * CC + oLo) * NN + n0 + mm;
            size_t offHi = ((size_t)b * CC + oHi) * NN + n0 + mm;
            if (Yh) {
                *(__half2*)&Yh[offLo] = __floats2half2_rn(v0.x, v0.y);
                *(__half2*)&Yh[offHi] = __floats2half2_rn(v1.x, v1.y);
            } else {
                *(float2*)&Y[offLo] = v0;
                *(float2*)&Y[offHi] = v1;
                sv[ci][0] += v0.x + v0.y;
                qv[ci][0] += v0.x * v0.x + v0.y * v0.y;
                sv[ci][1] += v1.x + v1.y;
                qv[ci][1] += v1.x * v1.x + v1.y * v1.y;
            }
        }
    }

    if (!Yh) {
#pragma unroll
        for (int ci = 0; ci < 2; ci++)
#pragma unroll
            for (int h = 0; h < 2; h++) {
                float s = sv[ci][h], q = qv[ci][h];
                s += __shfl_xor_sync(0xffffffffu, s, 1);
                s += __shfl_xor_sync(0xffffffffu, s, 2);
                q += __shfl_xor_sync(0xffffffffu, q, 1);
                q += __shfl_xor_sync(0xffffffffu, q, 2);
                if ((lane & 3) == 0) {
                    int oo = wc * 32 + ci * 16 + h * 8 + r0l;
                    sS[oo][wm] = s;
                    sQ[oo][wm] = q;
                }
            }
        __syncthreads();
        if (tid < 128) {
            g_bnpS[nb][b][tid] = sS[tid][0] + sS[tid][1];
            g_bnpQ[nb][b][tid] = sQ[tid][0] + sQ[tid][1];
        }
    }
}

// ---------------- fused energy + tile softmax (f16x2 ex2) ----------------------
__global__ __launch_bounds__(256, 2) void energy_softmax(
    const __half* __restrict__ QH, const __half* __restrict__ QL,
    const __half* __restrict__ QTH, const __half* __restrict__ QTL,
    const int* __restrict__ mask, __half* __restrict__ U)
{
    __shared__ __half Ah[64][40];
    __shared__ __half Al[64][40];
    __shared__ __half Bh[32][136];
    __shared__ __half Bl[32][136];
    __shared__ __half Us[64][136];
    __shared__ float  redu[64][4];
    __shared__ float  rowmax_s[64];
    __shared__ int    cms[128];
    __shared__ int    rms[64];

    const int b  = blockIdx.z;
    const int n0 = blockIdx.y * 64;
    const int m0 = blockIdx.x * 128;
    const int mt = blockIdx.x;
    const int tid = threadIdx.x;
    const int wid = tid >> 5, lane = tid & 31;
    const int wn = wid & 1, wm = wid >> 1;

    {
        int r = tid >> 2, s = tid & 3;
        size_t off = ((size_t)b * NN + n0 + r) * 32 + s * 8;
        *(uint4*)&Ah[r][s * 8] = *(const uint4*)&QTH[off];
        *(uint4*)&Al[r][s * 8] = *(const uint4*)&QTL[off];
    }
#pragma unroll
    for (int u = 0; u < 2; u++) {
        int idx = tid + u * 256;
        int r = idx >> 4, s = idx & 15;
        size_t off = ((size_t)b * 32 + r) * NN + m0 + s * 8;
        *(uint4*)&Bh[r][s * 8] = *(const uint4*)&QH[off];
        *(uint4*)&Bl[r][s * 8] = *(const uint4*)&QL[off];
    }
    if (tid < 128) cms[tid] = mask[(size_t)b * NN + m0 + tid];
    if (tid < 64)  rms[tid] = mask[(size_t)b * NN + n0 + tid];
    __syncthreads();

    float acc[2][4][4];
#pragma unroll
    for (int i = 0; i < 2; i++)
#pragma unroll
        for (int j = 0; j < 4; j++)
#pragma unroll
            for (int k = 0; k < 4; k++) acc[i][j][k] = 0.f;

    const int lrow = (lane & 7) + ((lane >> 3) & 1) * 8;
    const int lsel = lane >> 4;
    const int g = lane >> 3;
    const int r0l = lane >> 2, c0l = (lane & 3) * 2;

#pragma unroll
    for (int kk = 0; kk < 2; kk++) {
        unsigned ah[2][4], al[2][4];
#pragma unroll
        for (int ci = 0; ci < 2; ci++) {
            ldsm_x4(ah[ci][0], ah[ci][1], ah[ci][2], ah[ci][3],
                    &Ah[wn * 32 + ci * 16 + lrow][kk * 16 + lsel * 8]);
            ldsm_x4(al[ci][0], al[ci][1], al[ci][2], al[ci][3],
                    &Al[wn * 32 + ci * 16 + lrow][kk * 16 + lsel * 8]);
        }
        unsigned bh[4][2], bl[4][2];
#pragma unroll
        for (int h = 0; h < 2; h++) {
            unsigned t0, t1, t2, t3;
            ldsm_x4_t(t0, t1, t2, t3,
                      &Bh[kk * 16 + (g & 1) * 8 + (lane & 7)][wm * 32 + h * 16 + (g >> 1) * 8]);
            bh[h * 2 + 0][0] = t0; bh[h * 2 + 0][1] = t1;
            bh[h * 2 + 1][0] = t2; bh[h * 2 + 1][1] = t3;
            ldsm_x4_t(t0, t1, t2, t3,
                      &Bl[kk * 16 + (g & 1) * 8 + (lane & 7)][wm * 32 + h * 16 + (g >> 1) * 8]);
            bl[h * 2 + 0][0] = t0; bl[h * 2 + 0][1] = t1;
            bl[h * 2 + 1][0] = t2; bl[h * 2 + 1][1] = t3;
        }
#pragma unroll
        for (int ci = 0; ci < 2; ci++)
#pragma unroll
            for (int nf = 0; nf < 4; nf++) {
                mma16816(acc[ci][nf], ah[ci], bh[nf]);
                mma16816(acc[ci][nf], ah[ci], bl[nf]);
                mma16816(acc[ci][nf], al[ci], bh[nf]);
            }
    }

    float vmax[2][2];
    vmax[0][0] = NEGV; vmax[0][1] = NEGV; vmax[1][0] = NEGV; vmax[1][1] = NEGV;
#pragma unroll
    for (int ci = 0; ci < 2; ci++)
#pragma unroll
        for (int nf = 0; nf < 4; nf++) {
            int mm = wm * 32 + nf * 8 + c0l;
            int cm0 = cms[mm], cm1 = cms[mm + 1];
#pragma unroll
            for (int h = 0; h < 2; h++) {
                int rm = rms[wn * 32 + ci * 16 + h * 8 + r0l];
                float v0 = (rm && cm0) ? acc[ci][nf][h * 2 + 0] : NEGV;
                float v1 = (rm && cm1) ? acc[ci][nf][h * 2 + 1] : NEGV;
                acc[ci][nf][h * 2 + 0] = v0;
                acc[ci][nf][h * 2 + 1] = v1;
                vmax[ci][h] = fmaxf(vmax[ci][h], fmaxf(v0, v1));
            }
        }
#pragma unroll
    for (int ci = 0; ci < 2; ci++)
#pragma unroll
        for (int h = 0; h < 2; h++) {
            float v = vmax[ci][h];
            v = fmaxf(v, __shfl_xor_sync(0xffffffffu, v, 1));
            v = fmaxf(v, __shfl_xor_sync(0xffffffffu, v, 2));
            vmax[ci][h] = v;
        }
    if ((lane & 3) == 0) {
#pragma unroll
        for (int ci = 0; ci < 2; ci++)
#pragma unroll
            for (int h = 0; h < 2; h++)
                redu[wn * 32 + ci * 16 + h * 8 + r0l][wm] = vmax[ci][h];
    }
    __syncthreads();
    if (tid < 64) {
        float v = fmaxf(fmaxf(redu[tid][0], redu[tid][1]),
                        fmaxf(redu[tid][2], redu[tid][3]));
        rowmax_s[tid] = v;
        g_tmax[((size_t)mt * BB + b) * NN + n0 + tid] = v;
    }
    __syncthreads();

    float mx_[2][2];
#pragma unroll
    for (int ci = 0; ci < 2; ci++)
#pragma unroll
        for (int h = 0; h < 2; h++)
            mx_[ci][h] = rowmax_s[wn * 32 + ci * 16 + h * 8 + r0l];

    float rsum[2][2] = {{0.f, 0.f}, {0.f, 0.f}};
#pragma unroll
    for (int ci = 0; ci < 2; ci++)
#pragma unroll
        for (int nf = 0; nf < 4; nf++) {
            int mm = wm * 32 + nf * 8 + c0l;
#pragma unroll
            for (int h = 0; h < 2; h++) {
                float x0 = (acc[ci][nf][h * 2 + 0] - mx_[ci][h]) * LOG2E;
                float x1 = (acc[ci][nf][h * 2 + 1] - mx_[ci][h]) * LOG2E;
                __half2 u2 = h2_ex2(__floats2half2_rn(x0, x1));
                int row = wn * 32 + ci * 16 + h * 8 + r0l;
                *(__half2*)&Us[row][mm] = u2;
                float2 uf = __half22float2(u2);
                rsum[ci][h] += uf.x + uf.y;
            }
        }
#pragma unroll
    for (int ci = 0; ci < 2; ci++)
#pragma unroll
        for (int h = 0; h < 2; h++) {
            float v = rsum[ci][h];
            v += __shfl_xor_sync(0xffffffffu, v, 1);
            v += __shfl_xor_sync(0xffffffffu, v, 2);
            rsum[ci][h] = v;
        }
    if ((lane & 3) == 0) {
#pragma unroll
        for (int ci = 0; ci < 2; ci++)
#pragma unroll
            for (int h = 0; h < 2; h++)
                redu[wn * 32 + ci * 16 + h * 8 + r0l][wm] = rsum[ci][h];
    }
    __syncthreads();
    if (tid < 64) {
        float s = (redu[tid][0] + redu[tid][1]) + (redu[tid][2] + redu[tid][3]);
        g_tsum[((size_t)mt * BB + b) * NN + n0 + tid] = s;
    }
#pragma unroll
    for (int u = 0; u < 4; u++) {
        int idx = tid + u * 256;
        int r = idx >> 4, s = idx & 15;
        *(uint4*)&U[((size_t)b * NN + n0 + r) * NN + m0 + s * 8] = *(uint4*)&Us[r][s * 8];
    }
}

// ---------------- rowscale -------------------------------------------------------
__global__ __launch_bounds__(256) void rowscale_kernel()
{
    const int b = blockIdx.y;
    const int n = blockIdx.x * 256 + threadIdx.x;
    float mx[32];
    float m_row;
#pragma unroll
    for (int t = 0; t < 32; t++) {
        mx[t] = g_tmax[((size_t)t * BB + b) * NN + n];
        m_row = (t == 0) ? mx[0] : fmaxf(m_row, mx[t]);
    }
    float s = 0.f;
    float ex[32];
#pragma unroll
    for (int t = 0; t < 32; t++) {
        ex[t] = __expf(mx[t] - m_row);
        s += ex[t] * g_tsum[((size_t)t * BB + b) * NN + n];
    }
    float inv = FSCALE / s;
#pragma unroll
    for (int t = 0; t < 32; t++)
        g_rowscale[((size_t)t * BB + b) * NN + n] = __float2half_rn(ex[t] * inv);
}

// ---------------- attn apply via HMMA, software-pipelined u loads --------------
__global__ __launch_bounds__(256, 2) void apply_hmma(
    const __half* __restrict__ XVH, const __half* __restrict__ U,
    float* __restrict__ XR)
{
    __shared__ __half XVs[128][72];
    __shared__ __half As[64][72];
    __shared__ float  cs_s[32][68];
    __shared__ float  cinv_s[64];

    const int b  = blockIdx.y;
    const int m0 = blockIdx.x * 64;
    const int t  = blockIdx.x >> 1;
    const int tid = threadIdx.x;
    const int wid = tid >> 5, lane = tid & 31;
    const int wc = wid & 3, wm = wid >> 2;

    const __half* xv = XVH + (size_t)b * CC * NN;
    const __half* at = U + (size_t)b * NN * NN;
    const __half* fscale = g_rowscale + ((size_t)t * BB + b) * NN;

    float acc[2][4][4];
#pragma unroll
    for (int i = 0; i < 2; i++)
#pragma unroll
        for (int j = 0; j < 4; j++)
#pragma unroll
            for (int k = 0; k < 4; k++) acc[i][j][k] = 0.f;

    float2 cs2[4];
#pragma unroll
    for (int j = 0; j < 4; j++) cs2[j] = make_float2(0.f, 0.f);

    const int lrow = (lane & 7) + ((lane >> 3) & 1) * 8;
    const int lsel = lane >> 4;
    const int g = lane >> 3;

    const int ar0 = tid >> 3,        as0 = tid & 7;
    const int ar1 = (tid + 256) >> 3, as1 = (tid + 256) & 7;

    uint4  pA0 = *(const uint4*)&at[(size_t)ar0 * NN + m0 + as0 * 8];
    uint4  pA1 = *(const uint4*)&at[(size_t)ar1 * NN + m0 + as1 * 8];
    __half pF0 = fscale[ar0];
    __half pF1 = fscale[ar1];

    for (int k0 = 0; k0 < NN; k0 += 64) {
        if (k0) __syncthreads();

#pragma unroll
        for (int u = 0; u < 4; u++) {
            int idx = tid + u * 256;
            int r = idx >> 3, s = idx & 7;
            *(uint4*)&XVs[r][s * 8] = *(const uint4*)&xv[(size_t)r * NN + k0 + s * 8];
        }

        {
            __half2 f2 = __half2half2(pF0);
            const __half2* hp = (const __half2*)&pA0;
            __half2 outh[4];
#pragma unroll
            for (int j = 0; j < 4; j++) {
                __half2 prod = __hmul2(hp[j], f2);
                outh[j] = prod;
                float2 v = __half22float2(prod);
                cs2[j].x += v.x; cs2[j].y += v.y;
            }
            *(uint4*)&As[ar0][as0 * 8] = *(const uint4*)&outh[0];
        }
        {
            __half2 f2 = __half2half2(pF1);
            const __half2* hp = (const __half2*)&pA1;
            __half2 outh[4];
#pragma unroll
            for (int j = 0; j < 4; j++) {
                __half2 prod = __hmul2(hp[j], f2);
                outh[j] = prod;
                float2 v = __half22float2(prod);
                cs2[j].x += v.x; cs2[j].y += v.y;
            }
            *(uint4*)&As[ar1][as1 * 8] = *(const uint4*)&outh[0];
        }

        if (k0 + 64 < NN) {
            int kn = k0 + 64;
            pA0 = *(const uint4*)&at[(size_t)(kn + ar0) * NN + m0 + as0 * 8];
            pA1 = *(const uint4*)&at[(size_t)(kn + ar1) * NN + m0 + as1 * 8];
            pF0 = fscale[kn + ar0];
            pF1 = fscale[kn + ar1];
        }
        __syncthreads();

#pragma unroll
        for (int kk = 0; kk < 4; kk++) {
            unsigned a[2][4];
#pragma unroll
            for (int ci = 0; ci < 2; ci++)
                ldsm_x4(a[ci][0], a[ci][1], a[ci][2], a[ci][3],
                        &XVs[wc * 32 + ci * 16 + lrow][kk * 16 + lsel * 8]);
            unsigned bf[4][2];
#pragma unroll
            for (int h = 0; h < 2; h++) {
                unsigned t0, t1, t2, t3;
                ldsm_x4_t(t0, t1, t2, t3,
                          &As[kk * 16 + (g & 1) * 8 + (lane & 7)][wm * 32 + h * 16 + (g >> 1) * 8]);
                bf[h * 2 + 0][0] = t0; bf[h * 2 + 0][1] = t1;
                bf[h * 2 + 1][0] = t2; bf[h * 2 + 1][1] = t3;
            }
#pragma unroll
            for (int ci = 0; ci < 2; ci++)
#pragma unroll
                for (int nf = 0; nf < 4; nf++)
                    mma16816(acc[ci][nf], a[ci], bf[nf]);
        }
    }
    __syncthreads();

    {
        int gg = tid >> 3, s = tid & 7;
#pragma unroll
        for (int j = 0; j < 4; j++) {
            cs_s[gg][s * 8 + 2 * j]     = cs2[j].x;
            cs_s[gg][s * 8 + 2 * j + 1] = cs2[j].y;
        }
    }
    __syncthreads();
    if (tid < 64) {
        float tot = 0.f;
#pragma unroll
        for (int gg = 0; gg < 32; gg++) tot += cs_s[gg][tid];
        cinv_s[tid] = 1.f / (1e-9f + tot);
    }
    __syncthreads();

    const int r0l = lane >> 2, c0l = (lane & 3) * 2;
#pragma unroll
    for (int ci = 0; ci < 2; ci++) {
#pragma unroll
        for (int nf = 0; nf < 4; nf++) {
            int c = wc * 32 + ci * 16 + r0l;
            int mm = wm * 32 + nf * 8 + c0l;
            float2 cv = *(const float2*)&cinv_s[mm];
            float2 lo = make_float2(acc[ci][nf][0] * cv.x, acc[ci][nf][1] * cv.y);
            *(float2*)&XR[((size_t)b * CC + c) * NN + m0 + mm] = lo;
            float2 hi = make_float2(acc[ci][nf][2] * cv.x, acc[ci][nf][3] * cv.y);
            *(float2*)&XR[((size_t)b * CC + c + 8) * NN + m0 + mm] = hi;
        }
    }
}

// ---------------- BN finalize from gemm partials --------------------------------
__global__ void bn_finalize_kernel(const float* __restrict__ gam, const float* __restrict__ bet)
{
    const int c = threadIdx.x;
    float ts = 0.f, t2 = 0.f;
    for (int i = 0; i < 64; i++)
#pragma unroll
        for (int b = 0; b < BB; b++) {
            ts += g_bnpS[i][b][c];
            t2 += g_bnpQ[i][b][c];
        }
    const float invN = 1.f / (float)(BB * NN);
    float mean = ts * invN;
    float var  = t2 * invN - mean * mean;
    float sc = gam[c] * rsqrtf(var + 1e-5f);
    g_scale[c] = sc;
    g_shift[c] = bet[c] - mean * sc;
}

// ---------------- BN apply (+relu) [+residual into h and output slab] -----------
__global__ __launch_bounds__(256) void bn_apply_kernel(
    const float* __restrict__ Y, float* __restrict__ H,
    float* __restrict__ OUT, int layer)
{
    size_t f = ((size_t)blockIdx.x * 256 + threadIdx.x) * 4;
    int n = (int)(f % NN);
    int c = (int)((f / NN) % CC);
    int b = (int)(f / ((size_t)NN * CC));
    float sc = g_scale[c], sh = g_shift[c];
    float4 y = *(const float4*)&Y[f];
    float4 r;
    r.x = fmaxf(fmaf(y.x, sc, sh), 0.f);
    r.y = fmaxf(fmaf(y.y, sc, sh), 0.f);
    r.z = fmaxf(fmaf(y.z, sc, sh), 0.f);
    r.w = fmaxf(fmaf(y.w, sc, sh), 0.f);
    if (OUT) {
        float4 h = *(const float4*)&H[f];
        r.x += h.x; r.y += h.y; r.z += h.z; r.w += h.w;
        *(float4*)&H[f] = r;
        *(float4*)&OUT[(((size_t)b * 4 * CC) + (size_t)layer * CC + c) * NN + n] = r;
    } else {
        *(float4*)&H[f] = r;
    }
}

// ---------------- launch ---------------------------------------------------------
extern "C" void kernel_launch(void* const* d_in, const int* in_sizes, int n_in,
                              void* d_out, int out_size)
{
    const float* x    = (const float*)d_in[0];
    const int*   mask = (const int*)  d_in[1];
    const float* w1   = (const float*)d_in[2];
    const float* g1   = (const float*)d_in[3];
    const float* b1   = (const float*)d_in[4];
    const float* w2   = (const float*)d_in[5];
    const float* g2   = (const float*)d_in[6];
    const float* b2   = (const float*)d_in[7];
    const float* wqk  = (const float*)d_in[8];
    const float* wv   = (const float*)d_in[9];
    const float* bv   = (const float*)d_in[10];
    const float* wt   = (const float*)d_in[11];
    const float* bt   = (const float*)d_in[12];
    const float* sg   = (const float*)d_in[13];
    const float* sb   = (const float*)d_in[14];
    float* out = (float*)d_out;

    float *p_h, *p_y, *p_xr;
    __half *p_xvh, *p_u, *p_qh, *p_ql, *p_qth, *p_qtl;
    cudaGetSymbolAddress((void**)&p_h,   g_h);
    cudaGetSymbolAddress((void**)&p_y,   g_y);
    cudaGetSymbolAddress((void**)&p_xvh, g_xvh);
    cudaGetSymbolAddress((void**)&p_xr,  g_xr);
    cudaGetSymbolAddress((void**)&p_u,   g_u);
    cudaGetSymbolAddress((void**)&p_qh,  g_qh);
    cudaGetSymbolAddress((void**)&p_ql,  g_ql);
    cudaGetSymbolAddress((void**)&p_qth, g_qth);
    cudaGetSymbolAddress((void**)&p_qtl, g_qtl);

    const dim3 blk256(256);
    const dim3 grid_gh(NN / 64, BB);
    const dim3 grid_qk(NN / 64, 1, BB);
    const dim3 grid_es(NN / 128, NN / 64, BB);
    const dim3 grid_rs(NN / 256, BB);
    const dim3 grid_ap(NN / 64, BB);
    const dim3 grid_ba((unsigned)(((size_t)BB * CC * NN / 4) / 256));

    // head: two conv+BN+relu
    gemm_hmma<<<grid_gh, blk256>>>(w1, x, nullptr, nullptr, p_y, nullptr);
    bn_finalize_kernel<<<1, CC>>>(g1, b1);
    bn_apply_kernel<<<grid_ba, blk256>>>(p_y, p_h, nullptr, 0);

    gemm_hmma<<<grid_gh, blk256>>>(w2, p_h, nullptr, nullptr, p_y, nullptr);
    bn_finalize_kernel<<<1, CC>>>(g2, b2);
    bn_apply_kernel<<<grid_ba, blk256>>>(p_y, p_h, nullptr, 0);

    // 4 offset-attention layers
    for (int i = 0; i < 4; i++) {
        gemm_qk<<<grid_qk, blk256>>>(wqk + (size_t)i * 32 * CC, p_h, p_qh, p_ql, p_qth, p_qtl);
        energy_softmax<<<grid_es, blk256>>>(p_qh, p_ql, p_qth, p_qtl, mask, p_u);
        rowscale_kernel<<<grid_rs, blk256>>>();
        gemm_hmma<<<grid_gh, blk256>>>(wv + (size_t)i * CC * CC, p_h, nullptr, bv + (size_t)i * CC,
                                       nullptr, p_xvh);
        apply_hmma<<<grid_ap, blk256>>>(p_xvh, p_u, p_xr);
        gemm_hmma<<<grid_gh, blk256>>>(wt + (size_t)i * CC * CC, p_h, p_xr, bt + (size_t)i * CC,
                                       p_y, nullptr);
        bn_finalize_kernel<<<1, CC>>>(sg + (size_t)i * CC, sb + (size_t)i * CC);
        bn_apply_kernel<<<grid_ba, blk256>>>(p_y, p_h, out, i);
    }
}

// round 15
// speedup vs baseline: 1.2376x; 1.0469x over previous
#include <cuda_runtime.h>
#include <cuda_fp16.h>
#include <cstdint>
#include <cstddef>

#define NN 4096
#define CC 128
#define BB 4
#define NEGV (-9e15f)
#define LOG2E 1.4426950408889634f
#define FSCALE 256.0f

typedef unsigned long long ull;

// ---------------- scratch (device globals: no allocation allowed) -----------
__device__ float  g_h[(size_t)BB * CC * NN];                 // 8 MB
__device__ float  g_y[(size_t)BB * CC * NN];                 // 8 MB
__device__ __half g_qh[(size_t)BB * 32 * NN];                // 1 MB
__device__ __half g_ql[(size_t)BB * 32 * NN];                // 1 MB
__device__ __half g_qth[(size_t)BB * NN * 32];               // 1 MB
__device__ __half g_qtl[(size_t)BB * NN * 32];               // 1 MB
__device__ __half g_xvh[(size_t)BB * CC * NN];               // 4 MB
__device__ float  g_xr[(size_t)BB * CC * NN];                // 8 MB
__device__ __half g_u[(size_t)BB * NN * NN];                 // 128 MB
__device__ float  g_tmax[(size_t)32 * BB * NN];
__device__ float  g_tsum[(size_t)32 * BB * NN];
__device__ __half g_rowscale[(size_t)32 * BB * NN];
__device__ float  g_scale[CC];
__device__ float  g_shift[CC];
__device__ float  g_bnpS[64][BB][CC];
__device__ float  g_bnpQ[64][BB][CC];

// ---------------- helpers ----------------------------------------------------
__device__ __forceinline__ void fma2(ull& acc, ull a, ull b) {
    asm("fma.rn.f32x2 %0, %1, %2, %0;" : "+l"(acc) : "l"(a), "l"(b));
}
__device__ __forceinline__ ull pack2(float v) {
    ull r;
    unsigned u = __float_as_uint(v);
    asm("mov.b64 %0, {%1, %1};" : "=l"(r) : "r"(u));
    return r;
}
__device__ __forceinline__ float2 unpack2(ull v) {
    unsigned lo, hi;
    asm("mov.b64 {%0, %1}, %2;" : "=r"(lo), "=r"(hi) : "l"(v));
    return make_float2(__uint_as_float(lo), __uint_as_float(hi));
}
__device__ __forceinline__ __half2 h2_ex2(__half2 x) {
    unsigned xi = *(unsigned*)&x;
    unsigned ri;
    asm("ex2.approx.f16x2 %0, %1;" : "=r"(ri) : "r"(xi));
    return *(__half2*)&ri;
}
__device__ __forceinline__ void split2(float a, float b, __half2& h, __half2& l) {
    __half ha = __float2half_rn(a), hb = __float2half_rn(b);
    __half la = __float2half_rn(a - __half2float(ha));
    __half lb = __float2half_rn(b - __half2float(hb));
    h = __halves2half2(ha, hb);
    l = __halves2half2(la, lb);
}

// ---------------- HMMA helpers -------------------------------------------------
__device__ __forceinline__ void ldsm_x4(unsigned& r0, unsigned& r1, unsigned& r2, unsigned& r3,
                                        const void* p) {
    unsigned addr = (unsigned)__cvta_generic_to_shared(p);
    asm volatile("ldmatrix.sync.aligned.m8n8.x4.shared.b16 {%0,%1,%2,%3}, [%4];"
        : "=r"(r0), "=r"(r1), "=r"(r2), "=r"(r3) : "r"(addr));
}
__device__ __forceinline__ void ldsm_x4_t(unsigned& r0, unsigned& r1, unsigned& r2, unsigned& r3,
                                          const void* p) {
    unsigned addr = (unsigned)__cvta_generic_to_shared(p);
    asm volatile("ldmatrix.sync.aligned.m8n8.x4.trans.shared.b16 {%0,%1,%2,%3}, [%4];"
        : "=r"(r0), "=r"(r1), "=r"(r2), "=r"(r3) : "r"(addr));
}
__device__ __forceinline__ void mma16816(float d[4], const unsigned a[4], const unsigned b[2]) {
    asm volatile("mma.sync.aligned.m16n8k16.row.col.f32.f16.f16.f32 "
        "{%0,%1,%2,%3}, {%4,%5,%6,%7}, {%8,%9}, {%0,%1,%2,%3};"
        : "+f"(d[0]), "+f"(d[1]), "+f"(d[2]), "+f"(d[3])
        : "r"(a[0]), "r"(a[1]), "r"(a[2]), "r"(a[3]), "r"(b[0]), "r"(b[1]));
}

// ---------------- gemm_qk: q = Wqk (32xC) * X; FMA2; fp16 hi/lo + transposed ---
__global__ __launch_bounds__(256, 3) void gemm_qk(
    const float* __restrict__ W, const float* __restrict__ X,
    __half* __restrict__ QH, __half* __restrict__ QL,
    __half* __restrict__ QTH, __half* __restrict__ QTL)
{
    __shared__ float Ws[CC][36];
    __shared__ __align__(16) double Xd[64][34];

    const int b  = blockIdx.z;
    const int n0 = blockIdx.x * 64;
    const int tid = threadIdx.x;
    const int to = tid >> 4;
    const int tp = tid & 15;

    for (int idx = tid; idx < 32 * CC; idx += 256) {
        int o = idx / CC, c = idx % CC;
        Ws[c][o] = W[(size_t)o * CC + c];
    }

    const float* x1 = X + (size_t)b * CC * NN;

    ull acc[2][2];
    acc[0][0] = acc[0][1] = acc[1][0] = acc[1][1] = 0ull;

    for (int c0 = 0; c0 < CC; c0 += 64) {
        __syncthreads();
#pragma unroll
        for (int t = 0; t < 4; t++) {
            int idx = tid + t * 256;
            int c = idx >> 4, q = idx & 15;
            float4 v = *(const float4*)&x1[(size_t)(c0 + c) * NN + n0 + q * 4];
            *(double2*)&Xd[c][q * 2] = *(const double2*)&v;
        }
        __syncthreads();
#pragma unroll 8
        for (int k = 0; k < 64; k++) {
            float2 w2 = *(const float2*)&Ws[c0 + k][to * 2];
            ull xc0 = pack2(w2.x), xc1 = pack2(w2.y);
            double2 ad = *(const double2*)&Xd[k][2 * tp];
            ull a0 = *(const ull*)&ad.x;
            ull a1 = *(const ull*)&ad.y;
            fma2(acc[0][0], xc0, a0); fma2(acc[0][1], xc0, a1);
            fma2(acc[1][0], xc1, a0); fma2(acc[1][1], xc1, a1);
        }
    }

    __half h[2][2][2], l[2][2][2];
#pragma unroll
    for (int i = 0; i < 2; i++)
#pragma unroll
        for (int j = 0; j < 2; j++) {
            float2 v = unpack2(acc[i][j]);
            h[i][j][0] = __float2half_rn(v.x);
            l[i][j][0] = __float2half_rn(v.x - __half2float(h[i][j][0]));
            h[i][j][1] = __float2half_rn(v.y);
            l[i][j][1] = __float2half_rn(v.y - __half2float(h[i][j][1]));
        }

#pragma unroll
    for (int i = 0; i < 2; i++) {
        int o = to * 2 + i;
#pragma unroll
        for (int j = 0; j < 2; j++) {
            size_t off = ((size_t)b * 32 + o) * NN + n0 + 4 * tp + 2 * j;
            *(__half2*)&QH[off] = __halves2half2(h[i][j][0], h[i][j][1]);
            *(__half2*)&QL[off] = __halves2half2(l[i][j][0], l[i][j][1]);
        }
    }
#pragma unroll
    for (int j = 0; j < 2; j++)
#pragma unroll
        for (int xy = 0; xy < 2; xy++) {
            int n = n0 + 4 * tp + 2 * j + xy;
            size_t off = ((size_t)b * NN + n) * 32 + to * 2;
            *(__half2*)&QTH[off] = __halves2half2(h[0][j][xy], h[1][j][xy]);
            *(__half2*)&QTL[off] = __halves2half2(l[0][j][xy], l[1][j][xy]);
        }
}

// ---------------- gemm_hmma: Y[b,o,n] = sum_c W[o,c]*(X1-X2)[b,c,n] + bias -----
// Register-prefetched X loads (chunk i+1's raw floats load during chunk i MMAs).
__global__ __launch_bounds__(256, 2) void gemm_hmma(
    const float* __restrict__ W, const float* __restrict__ X1,
    const float* __restrict__ X2, const float* __restrict__ bias,
    float* __restrict__ Y, __half* __restrict__ Yh)
{
    __shared__ __half Wh[128][40];
    __shared__ __half Wl[128][40];
    __shared__ __half Xh[32][72];
    __shared__ __half Xl[32][72];
    __shared__ float  sS[128][2];
    __shared__ float  sQ[128][2];

    const int b  = blockIdx.y;
    const int nb = blockIdx.x;
    const int n0 = nb * 64;
    const int tid = threadIdx.x;
    const int wid = tid >> 5, lane = tid & 31;
    const int wc = wid & 3, wm = wid >> 2;

    const float* x1 = X1 + (size_t)b * CC * NN;
    const float* x2 = X2 ? X2 + (size_t)b * CC * NN : nullptr;

    float acc[2][4][4];
#pragma unroll
    for (int i = 0; i < 2; i++)
#pragma unroll
        for (int j = 0; j < 4; j++)
#pragma unroll
            for (int k = 0; k < 4; k++) acc[i][j][k] = 0.f;

    const int lrow = (lane & 7) + ((lane >> 3) & 1) * 8;
    const int lsel = lane >> 4;
    const int g = lane >> 3;

    const int xr0 = tid >> 4,         xs0 = tid & 15;
    const int xr1 = (tid + 256) >> 4, xs1 = (tid + 256) & 15;

    float4 pv0 = *(const float4*)&x1[(size_t)xr0 * NN + n0 + xs0 * 4];
    float4 pv1 = *(const float4*)&x1[(size_t)xr1 * NN + n0 + xs1 * 4];
    float4 pw0, pw1;
    if (x2) {
        pw0 = *(const float4*)&x2[(size_t)xr0 * NN + n0 + xs0 * 4];
        pw1 = *(const float4*)&x2[(size_t)xr1 * NN + n0 + xs1 * 4];
    }

    for (int c0 = 0; c0 < CC; c0 += 32) {
        if (c0) __syncthreads();

#pragma unroll
        for (int u = 0; u < 2; u++) {
            int idx = tid + u * 256;
            int o = idx >> 2, kg = idx & 3;
            const float* wsrc = W + (size_t)o * CC + c0 + kg * 8;
            float4 w0 = *(const float4*)&wsrc[0];
            float4 w1 = *(const float4*)&wsrc[4];
            __half2 hh[4], ll[4];
            split2(w0.x, w0.y, hh[0], ll[0]);
            split2(w0.z, w0.w, hh[1], ll[1]);
            split2(w1.x, w1.y, hh[2], ll[2]);
            split2(w1.z, w1.w, hh[3], ll[3]);
            *(uint4*)&Wh[o][kg * 8] = *(const uint4*)&hh[0];
            *(uint4*)&Wl[o][kg * 8] = *(const uint4*)&ll[0];
        }

        {
            float4 v = pv0;
            if (x2) { v.x -= pw0.x; v.y -= pw0.y; v.z -= pw0.z; v.w -= pw0.w; }
            __half2 hh[2], ll[2];
            split2(v.x, v.y, hh[0], ll[0]);
            split2(v.z, v.w, hh[1], ll[1]);
            *(uint2*)&Xh[xr0][xs0 * 4] = *(const uint2*)&hh[0];
            *(uint2*)&Xl[xr0][xs0 * 4] = *(const uint2*)&ll[0];
        }
        {
            float4 v = pv1;
            if (x2) { v.x -= pw1.x; v.y -= pw1.y; v.z -= pw1.z; v.w -= pw1.w; }
            __half2 hh[2], ll[2];
            split2(v.x, v.y, hh[0], ll[0]);
            split2(v.z, v.w, hh[1], ll[1]);
            *(uint2*)&Xh[xr1][xs1 * 4] = *(const uint2*)&hh[0];
            *(uint2*)&Xl[xr1][xs1 * 4] = *(const uint2*)&ll[0];
        }

        if (c0 + 32 < CC) {
            int cn = c0 + 32;
            pv0 = *(const float4*)&x1[(size_t)(cn + xr0) * NN + n0 + xs0 * 4];
            pv1 = *(const float4*)&x1[(size_t)(cn + xr1) * NN + n0 + xs1 * 4];
            if (x2) {
                pw0 = *(const float4*)&x2[(size_t)(cn + xr0) * NN + n0 + xs0 * 4];
                pw1 = *(const float4*)&x2[(size_t)(cn + xr1) * NN + n0 + xs1 * 4];
            }
        }
        __syncthreads();

#pragma unroll
        for (int kk = 0; kk < 2; kk++) {
            unsigned ah[2][4], al[2][4];
#pragma unroll
            for (int ci = 0; ci < 2; ci++) {
                ldsm_x4(ah[ci][0], ah[ci][1], ah[ci][2], ah[ci][3],
                        &Wh[wc * 32 + ci * 16 + lrow][kk * 16 + lsel * 8]);
                ldsm_x4(al[ci][0], al[ci][1], al[ci][2], al[ci][3],
                        &Wl[wc * 32 + ci * 16 + lrow][kk * 16 + lsel * 8]);
            }
            unsigned bh[4][2], bl[4][2];
#pragma unroll
            for (int h = 0; h < 2; h++) {
                unsigned t0, t1, t2, t3;
                ldsm_x4_t(t0, t1, t2, t3,
                          &Xh[kk * 16 + (g & 1) * 8 + (lane & 7)][wm * 32 + h * 16 + (g >> 1) * 8]);
                bh[h * 2 + 0][0] = t0; bh[h * 2 + 0][1] = t1;
                bh[h * 2 + 1][0] = t2; bh[h * 2 + 1][1] = t3;
                ldsm_x4_t(t0, t1, t2, t3,
                          &Xl[kk * 16 + (g & 1) * 8 + (lane & 7)][wm * 32 + h * 16 + (g >> 1) * 8]);
                bl[h * 2 + 0][0] = t0; bl[h * 2 + 0][1] = t1;
                bl[h * 2 + 1][0] = t2; bl[h * 2 + 1][1] = t3;
            }
#pragma unroll
            for (int ci = 0; ci < 2; ci++)
#pragma unroll
                for (int nf = 0; nf < 4; nf++) {
                    mma16816(acc[ci][nf], ah[ci], bh[nf]);
                    mma16816(acc[ci][nf], ah[ci], bl[nf]);
                    mma16816(acc[ci][nf], al[ci], bh[nf]);
                }
        }
    }
    __syncthreads();

    const int r0l = lane >> 2, c0l = (lane & 3) * 2;
    float sv[2][2] = {{0.f, 0.f}, {0.f, 0.f}};
    float qv[2][2] = {{0.f, 0.f}, {0.f, 0.f}};

#pragma unroll
    for (int ci = 0; ci < 2; ci++) {
        int oLo = wc * 32 + ci * 16 + r0l;
        int oHi = oLo + 8;
        float biLo = bias ? bias[oLo] : 0.f;
        float biHi = bias ? bias[oHi] : 0.f;
#pragma unroll
        for (int nf = 0; nf < 4; nf++) {
            int mm = wm * 32 + nf * 8 + c0l;
            float2 v0 = make_float2(acc[ci][nf][0] + biLo, acc[ci][nf][1] + biLo);
            float2 v1 = make_float2(acc[ci][nf][2] + biHi, acc[ci][nf][3] + biHi);
            size_t offLo = ((size_t)b * CC + oLo) * NN + n0 + mm;
            size_t offHi = ((size_t)b * CC + oHi) * NN + n0 + mm;
            if (Yh) {
                *(__half2*)&Yh[offLo] = __floats2half2_rn(v0.x, v0.y);
                *(__half2*)&Yh[offHi] = __floats2half2_rn(v1.x, v1.y);
            } else {
                *(float2*)&Y[offLo] = v0;
                *(float2*)&Y[offHi] = v1;
                sv[ci][0] += v0.x + v0.y;
                qv[ci][0] += v0.x * v0.x + v0.y * v0.y;
                sv[ci][1] += v1.x + v1.y;
                qv[ci][1] += v1.x * v1.x + v1.y * v1.y;
            }
        }
    }

    if (!Yh) {
#pragma unroll
        for (int ci = 0; ci < 2; ci++)
#pragma unroll
            for (int h = 0; h < 2; h++) {
                float s = sv[ci][h], q = qv[ci][h];
                s += __shfl_xor_sync(0xffffffffu, s, 1);
                s += __shfl_xor_sync(0xffffffffu, s, 2);
                q += __shfl_xor_sync(0xffffffffu, q, 1);
                q += __shfl_xor_sync(0xffffffffu, q, 2);
                if ((lane & 3) == 0) {
                    int oo = wc * 32 + ci * 16 + h * 8 + r0l;
                    sS[oo][wm] = s;
                    sQ[oo][wm] = q;
                }
            }
        __syncthreads();
        if (tid < 128) {
            g_bnpS[nb][b][tid] = sS[tid][0] + sS[tid][1];
            g_bnpQ[nb][b][tid] = sQ[tid][0] + sQ[tid][1];
        }
    }
}

// ---------------- fused energy + tile softmax (f16x2 ex2) ----------------------
// smem: Us aliases Bh/Bl (safe: first Us write happens two barriers after the
// last B read). 29.7 KB smem + 84-reg cap -> 3 CTAs/SM.
__global__ __launch_bounds__(256, 3) void energy_softmax(
    const __half* __restrict__ QH, const __half* __restrict__ QL,
    const __half* __restrict__ QTH, const __half* __restrict__ QTL,
    const int* __restrict__ mask, __half* __restrict__ U)
{
    __shared__ __align__(16) char smraw[29696];
    __half (*Ah)[40]  = (__half(*)[40])(smraw);                // 5120
    __half (*Al)[40]  = (__half(*)[40])(smraw + 5120);         // 5120
    __half (*Bh)[136] = (__half(*)[136])(smraw + 10240);       // 8704
    __half (*Bl)[136] = (__half(*)[136])(smraw + 18944);       // 8704
    __half (*Us)[136] = (__half(*)[136])(smraw + 10240);       // ALIASES Bh/Bl (17408)
    float (*redu)[4]  = (float(*)[4])(smraw + 27648);          // 1024
    float* rowmax_s   = (float*)(smraw + 28672);               // 256
    int*   cms        = (int*)(smraw + 28928);                 // 512
    int*   rms        = (int*)(smraw + 29440);                 // 256

    const int b  = blockIdx.z;
    const int n0 = blockIdx.y * 64;
    const int m0 = blockIdx.x * 128;
    const int mt = blockIdx.x;
    const int tid = threadIdx.x;
    const int wid = tid >> 5, lane = tid & 31;
    const int wn = wid & 1, wm = wid >> 1;

    {
        int r = tid >> 2, s = tid & 3;
        size_t off = ((size_t)b * NN + n0 + r) * 32 + s * 8;
        *(uint4*)&Ah[r][s * 8] = *(const uint4*)&QTH[off];
        *(uint4*)&Al[r][s * 8] = *(const uint4*)&QTL[off];
    }
#pragma unroll
    for (int u = 0; u < 2; u++) {
        int idx = tid + u * 256;
        int r = idx >> 4, s = idx & 15;
        size_t off = ((size_t)b * 32 + r) * NN + m0 + s * 8;
        *(uint4*)&Bh[r][s * 8] = *(const uint4*)&QH[off];
        *(uint4*)&Bl[r][s * 8] = *(const uint4*)&QL[off];
    }
    if (tid < 128) cms[tid] = mask[(size_t)b * NN + m0 + tid];
    if (tid < 64)  rms[tid] = mask[(size_t)b * NN + n0 + tid];
    __syncthreads();

    float acc[2][4][4];
#pragma unroll
    for (int i = 0; i < 2; i++)
#pragma unroll
        for (int j = 0; j < 4; j++)
#pragma unroll
            for (int k = 0; k < 4; k++) acc[i][j][k] = 0.f;

    const int lrow = (lane & 7) + ((lane >> 3) & 1) * 8;
    const int lsel = lane >> 4;
    const int g = lane >> 3;
    const int r0l = lane >> 2, c0l = (lane & 3) * 2;

#pragma unroll
    for (int kk = 0; kk < 2; kk++) {
        unsigned ah[2][4], al[2][4];
#pragma unroll
        for (int ci = 0; ci < 2; ci++) {
            ldsm_x4(ah[ci][0], ah[ci][1], ah[ci][2], ah[ci][3],
                    &Ah[wn * 32 + ci * 16 + lrow][kk * 16 + lsel * 8]);
            ldsm_x4(al[ci][0], al[ci][1], al[ci][2], al[ci][3],
                    &Al[wn * 32 + ci * 16 + lrow][kk * 16 + lsel * 8]);
        }
        unsigned bh[4][2], bl[4][2];
#pragma unroll
        for (int h = 0; h < 2; h++) {
            unsigned t0, t1, t2, t3;
            ldsm_x4_t(t0, t1, t2, t3,
                      &Bh[kk * 16 + (g & 1) * 8 + (lane & 7)][wm * 32 + h * 16 + (g >> 1) * 8]);
            bh[h * 2 + 0][0] = t0; bh[h * 2 + 0][1] = t1;
            bh[h * 2 + 1][0] = t2; bh[h * 2 + 1][1] = t3;
            ldsm_x4_t(t0, t1, t2, t3,
                      &Bl[kk * 16 + (g & 1) * 8 + (lane & 7)][wm * 32 + h * 16 + (g >> 1) * 8]);
            bl[h * 2 + 0][0] = t0; bl[h * 2 + 0][1] = t1;
            bl[h * 2 + 1][0] = t2; bl[h * 2 + 1][1] = t3;
        }
#pragma unroll
        for (int ci = 0; ci < 2; ci++)
#pragma unroll
            for (int nf = 0; nf < 4; nf++) {
                mma16816(acc[ci][nf], ah[ci], bh[nf]);
                mma16816(acc[ci][nf], ah[ci], bl[nf]);
                mma16816(acc[ci][nf], al[ci], bh[nf]);
            }
    }

    float vmax[2][2];
    vmax[0][0] = NEGV; vmax[0][1] = NEGV; vmax[1][0] = NEGV; vmax[1][1] = NEGV;
#pragma unroll
    for (int ci = 0; ci < 2; ci++)
#pragma unroll
        for (int nf = 0; nf < 4; nf++) {
            int mm = wm * 32 + nf * 8 + c0l;
            int cm0 = cms[mm], cm1 = cms[mm + 1];
#pragma unroll
            for (int h = 0; h < 2; h++) {
                int rm = rms[wn * 32 + ci * 16 + h * 8 + r0l];
                float v0 = (rm && cm0) ? acc[ci][nf][h * 2 + 0] : NEGV;
                float v1 = (rm && cm1) ? acc[ci][nf][h * 2 + 1] : NEGV;
                acc[ci][nf][h * 2 + 0] = v0;
                acc[ci][nf][h * 2 + 1] = v1;
                vmax[ci][h] = fmaxf(vmax[ci][h], fmaxf(v0, v1));
            }
        }
#pragma unroll
    for (int ci = 0; ci < 2; ci++)
#pragma unroll
        for (int h = 0; h < 2; h++) {
            float v = vmax[ci][h];
            v = fmaxf(v, __shfl_xor_sync(0xffffffffu, v, 1));
            v = fmaxf(v, __shfl_xor_sync(0xffffffffu, v, 2));
            vmax[ci][h] = v;
        }
    if ((lane & 3) == 0) {
#pragma unroll
        for (int ci = 0; ci < 2; ci++)
#pragma unroll
            for (int h = 0; h < 2; h++)
                redu[wn * 32 + ci * 16 + h * 8 + r0l][wm] = vmax[ci][h];
    }
    __syncthreads();
    if (tid < 64) {
        float v = fmaxf(fmaxf(redu[tid][0], redu[tid][1]),
                        fmaxf(redu[tid][2], redu[tid][3]));
        rowmax_s[tid] = v;
        g_tmax[((size_t)mt * BB + b) * NN + n0 + tid] = v;
    }
    __syncthreads();

    float mx_[2][2];
#pragma unroll
    for (int ci = 0; ci < 2; ci++)
#pragma unroll
        for (int h = 0; h < 2; h++)
            mx_[ci][h] = rowmax_s[wn * 32 + ci * 16 + h * 8 + r0l];

    float rsum[2][2] = {{0.f, 0.f}, {0.f, 0.f}};
#pragma unroll
    for (int ci = 0; ci < 2; ci++)
#pragma unroll
        for (int nf = 0; nf < 4; nf++) {
            int mm = wm * 32 + nf * 8 + c0l;
#pragma unroll
            for (int h = 0; h < 2; h++) {
                float x0 = (acc[ci][nf][h * 2 + 0] - mx_[ci][h]) * LOG2E;
                float x1 = (acc[ci][nf][h * 2 + 1] - mx_[ci][h]) * LOG2E;
                __half2 u2 = h2_ex2(__floats2half2_rn(x0, x1));
                int row = wn * 32 + ci * 16 + h * 8 + r0l;
                *(__half2*)&Us[row][mm] = u2;
                float2 uf = __half22float2(u2);
                rsum[ci][h] += uf.x + uf.y;
            }
        }
#pragma unroll
    for (int ci = 0; ci < 2; ci++)
#pragma unroll
        for (int h = 0; h < 2; h++) {
            float v = rsum[ci][h];
            v += __shfl_xor_sync(0xffffffffu, v, 1);
            v += __shfl_xor_sync(0xffffffffu, v, 2);
            rsum[ci][h] = v;
        }
    if ((lane & 3) == 0) {
#pragma unroll
        for (int ci = 0; ci < 2; ci++)
#pragma unroll
            for (int h = 0; h < 2; h++)
                redu[wn * 32 + ci * 16 + h * 8 + r0l][wm] = rsum[ci][h];
    }
    __syncthreads();
    if (tid < 64) {
        float s = (redu[tid][0] + redu[tid][1]) + (redu[tid][2] + redu[tid][3]);
        g_tsum[((size_t)mt * BB + b) * NN + n0 + tid] = s;
    }
#pragma unroll
    for (int u = 0; u < 4; u++) {
        int idx = tid + u * 256;
        int r = idx >> 4, s = idx & 15;
        *(uint4*)&U[((size_t)b * NN + n0 + r) * NN + m0 + s * 8] = *(uint4*)&Us[r][s * 8];
    }
}

// ---------------- rowscale -------------------------------------------------------
__global__ __launch_bounds__(256) void rowscale_kernel()
{
    const int b = blockIdx.y;
    const int n = blockIdx.x * 256 + threadIdx.x;
    float mx[32];
    float m_row;
#pragma unroll
    for (int t = 0; t < 32; t++) {
        mx[t] = g_tmax[((size_t)t * BB + b) * NN + n];
        m_row = (t == 0) ? mx[0] : fmaxf(m_row, mx[t]);
    }
    float s = 0.f;
    float ex[32];
#pragma unroll
    for (int t = 0; t < 32; t++) {
        ex[t] = __expf(mx[t] - m_row);
        s += ex[t] * g_tsum[((size_t)t * BB + b) * NN + n];
    }
    float inv = FSCALE / s;
#pragma unroll
    for (int t = 0; t < 32; t++)
        g_rowscale[((size_t)t * BB + b) * NN + n] = __float2half_rn(ex[t] * inv);
}

// ---------------- attn apply via HMMA, software-pipelined u loads --------------
__global__ __launch_bounds__(256, 2) void apply_hmma(
    const __half* __restrict__ XVH, const __half* __restrict__ U,
    float* __restrict__ XR)
{
    __shared__ __half XVs[128][72];
    __shared__ __half As[64][72];
    __shared__ float  cs_s[32][68];
    __shared__ float  cinv_s[64];

    const int b  = blockIdx.y;
    const int m0 = blockIdx.x * 64;
    const int t  = blockIdx.x >> 1;
    const int tid = threadIdx.x;
    const int wid = tid >> 5, lane = tid & 31;
    const int wc = wid & 3, wm = wid >> 2;

    const __half* xv = XVH + (size_t)b * CC * NN;
    const __half* at = U + (size_t)b * NN * NN;
    const __half* fscale = g_rowscale + ((size_t)t * BB + b) * NN;

    float acc[2][4][4];
#pragma unroll
    for (int i = 0; i < 2; i++)
#pragma unroll
        for (int j = 0; j < 4; j++)
#pragma unroll
            for (int k = 0; k < 4; k++) acc[i][j][k] = 0.f;

    float2 cs2[4];
#pragma unroll
    for (int j = 0; j < 4; j++) cs2[j] = make_float2(0.f, 0.f);

    const int lrow = (lane & 7) + ((lane >> 3) & 1) * 8;
    const int lsel = lane >> 4;
    const int g = lane >> 3;

    const int ar0 = tid >> 3,        as0 = tid & 7;
    const int ar1 = (tid + 256) >> 3, as1 = (tid + 256) & 7;

    uint4  pA0 = *(const uint4*)&at[(size_t)ar0 * NN + m0 + as0 * 8];
    uint4  pA1 = *(const uint4*)&at[(size_t)ar1 * NN + m0 + as1 * 8];
    __half pF0 = fscale[ar0];
    __half pF1 = fscale[ar1];

    for (int k0 = 0; k0 < NN; k0 += 64) {
        if (k0) __syncthreads();

#pragma unroll
        for (int u = 0; u < 4; u++) {
            int idx = tid + u * 256;
            int r = idx >> 3, s = idx & 7;
            *(uint4*)&XVs[r][s * 8] = *(const uint4*)&xv[(size_t)r * NN + k0 + s * 8];
        }

        {
            __half2 f2 = __half2half2(pF0);
            const __half2* hp = (const __half2*)&pA0;
            __half2 outh[4];
#pragma unroll
            for (int j = 0; j < 4; j++) {
                __half2 prod = __hmul2(hp[j], f2);
                outh[j] = prod;
                float2 v = __half22float2(prod);
                cs2[j].x += v.x; cs2[j].y += v.y;
            }
            *(uint4*)&As[ar0][as0 * 8] = *(const uint4*)&outh[0];
        }
        {
            __half2 f2 = __half2half2(pF1);
            const __half2* hp = (const __half2*)&pA1;
            __half2 outh[4];
#pragma unroll
            for (int j = 0; j < 4; j++) {
                __half2 prod = __hmul2(hp[j], f2);
                outh[j] = prod;
                float2 v = __half22float2(prod);
                cs2[j].x += v.x; cs2[j].y += v.y;
            }
            *(uint4*)&As[ar1][as1 * 8] = *(const uint4*)&outh[0];
        }

        if (k0 + 64 < NN) {
            int kn = k0 + 64;
            pA0 = *(const uint4*)&at[(size_t)(kn + ar0) * NN + m0 + as0 * 8];
            pA1 = *(const uint4*)&at[(size_t)(kn + ar1) * NN + m0 + as1 * 8];
            pF0 = fscale[kn + ar0];
            pF1 = fscale[kn + ar1];
        }
        __syncthreads();

#pragma unroll
        for (int kk = 0; kk < 4; kk++) {
            unsigned a[2][4];
#pragma unroll
            for (int ci = 0; ci < 2; ci++)
                ldsm_x4(a[ci][0], a[ci][1], a[ci][2], a[ci][3],
                        &XVs[wc * 32 + ci * 16 + lrow][kk * 16 + lsel * 8]);
            unsigned bf[4][2];
#pragma unroll
            for (int h = 0; h < 2; h++) {
                unsigned t0, t1, t2, t3;
                ldsm_x4_t(t0, t1, t2, t3,
                          &As[kk * 16 + (g & 1) * 8 + (lane & 7)][wm * 32 + h * 16 + (g >> 1) * 8]);
                bf[h * 2 + 0][0] = t0; bf[h * 2 + 0][1] = t1;
                bf[h * 2 + 1][0] = t2; bf[h * 2 + 1][1] = t3;
            }
#pragma unroll
            for (int ci = 0; ci < 2; ci++)
#pragma unroll
                for (int nf = 0; nf < 4; nf++)
                    mma16816(acc[ci][nf], a[ci], bf[nf]);
        }
    }
    __syncthreads();

    {
        int gg = tid >> 3, s = tid & 7;
#pragma unroll
        for (int j = 0; j < 4; j++) {
            cs_s[gg][s * 8 + 2 * j]     = cs2[j].x;
            cs_s[gg][s * 8 + 2 * j + 1] = cs2[j].y;
        }
    }
    __syncthreads();
    if (tid < 64) {
        float tot = 0.f;
#pragma unroll
        for (int gg = 0; gg < 32; gg++) tot += cs_s[gg][tid];
        cinv_s[tid] = 1.f / (1e-9f + tot);
    }
    __syncthreads();

    const int r0l = lane >> 2, c0l = (lane & 3) * 2;
#pragma unroll
    for (int ci = 0; ci < 2; ci++) {
#pragma unroll
        for (int nf = 0; nf < 4; nf++) {
            int c = wc * 32 + ci * 16 + r0l;
            int mm = wm * 32 + nf * 8 + c0l;
            float2 cv = *(const float2*)&cinv_s[mm];
            float2 lo = make_float2(acc[ci][nf][0] * cv.x, acc[ci][nf][1] * cv.y);
            *(float2*)&XR[((size_t)b * CC + c) * NN + m0 + mm] = lo;
            float2 hi = make_float2(acc[ci][nf][2] * cv.x, acc[ci][nf][3] * cv.y);
            *(float2*)&XR[((size_t)b * CC + c + 8) * NN + m0 + mm] = hi;
        }
    }
}

// ---------------- BN finalize from gemm partials --------------------------------
__global__ void bn_finalize_kernel(const float* __restrict__ gam, const float* __restrict__ bet)
{
    const int c = threadIdx.x;
    float ts = 0.f, t2 = 0.f;
    for (int i = 0; i < 64; i++)
#pragma unroll
        for (int b = 0; b < BB; b++) {
            ts += g_bnpS[i][b][c];
            t2 += g_bnpQ[i][b][c];
        }
    const float invN = 1.f / (float)(BB * NN);
    float mean = ts * invN;
    float var  = t2 * invN - mean * mean;
    float sc = gam[c] * rsqrtf(var + 1e-5f);
    g_scale[c] = sc;
    g_shift[c] = bet[c] - mean * sc;
}

// ---------------- BN apply (+relu) [+residual into h and output slab] -----------
__global__ __launch_bounds__(256) void bn_apply_kernel(
    const float* __restrict__ Y, float* __restrict__ H,
    float* __restrict__ OUT, int layer)
{
    size_t f = ((size_t)blockIdx.x * 256 + threadIdx.x) * 4;
    int n = (int)(f % NN);
    int c = (int)((f / NN) % CC);
    int b = (int)(f / ((size_t)NN * CC));
    float sc = g_scale[c], sh = g_shift[c];
    float4 y = *(const float4*)&Y[f];
    float4 r;
    r.x = fmaxf(fmaf(y.x, sc, sh), 0.f);
    r.y = fmaxf(fmaf(y.y, sc, sh), 0.f);
    r.z = fmaxf(fmaf(y.z, sc, sh), 0.f);
    r.w = fmaxf(fmaf(y.w, sc, sh), 0.f);
    if (OUT) {
        float4 h = *(const float4*)&H[f];
        r.x += h.x; r.y += h.y; r.z += h.z; r.w += h.w;
        *(float4*)&H[f] = r;
        *(float4*)&OUT[(((size_t)b * 4 * CC) + (size_t)layer * CC + c) * NN + n] = r;
    } else {
        *(float4*)&H[f] = r;
    }
}

// ---------------- launch ---------------------------------------------------------
extern "C" void kernel_launch(void* const* d_in, const int* in_sizes, int n_in,
                              void* d_out, int out_size)
{
    const float* x    = (const float*)d_in[0];
    const int*   mask = (const int*)  d_in[1];
    const float* w1   = (const float*)d_in[2];
    const float* g1   = (const float*)d_in[3];
    const float* b1   = (const float*)d_in[4];
    const float* w2   = (const float*)d_in[5];
    const float* g2   = (const float*)d_in[6];
    const float* b2   = (const float*)d_in[7];
    const float* wqk  = (const float*)d_in[8];
    const float* wv   = (const float*)d_in[9];
    const float* bv   = (const float*)d_in[10];
    const float* wt   = (const float*)d_in[11];
    const float* bt   = (const float*)d_in[12];
    const float* sg   = (const float*)d_in[13];
    const float* sb   = (const float*)d_in[14];
    float* out = (float*)d_out;

    float *p_h, *p_y, *p_xr;
    __half *p_xvh, *p_u, *p_qh, *p_ql, *p_qth, *p_qtl;
    cudaGetSymbolAddress((void**)&p_h,   g_h);
    cudaGetSymbolAddress((void**)&p_y,   g_y);
    cudaGetSymbolAddress((void**)&p_xvh, g_xvh);
    cudaGetSymbolAddress((void**)&p_xr,  g_xr);
    cudaGetSymbolAddress((void**)&p_u,   g_u);
    cudaGetSymbolAddress((void**)&p_qh,  g_qh);
    cudaGetSymbolAddress((void**)&p_ql,  g_ql);
    cudaGetSymbolAddress((void**)&p_qth, g_qth);
    cudaGetSymbolAddress((void**)&p_qtl, g_qtl);

    const dim3 blk256(256);
    const dim3 grid_gh(NN / 64, BB);
    const dim3 grid_qk(NN / 64, 1, BB);
    const dim3 grid_es(NN / 128, NN / 64, BB);
    const dim3 grid_rs(NN / 256, BB);
    const dim3 grid_ap(NN / 64, BB);
    const dim3 grid_ba((unsigned)(((size_t)BB * CC * NN / 4) / 256));

    // head: two conv+BN+relu
    gemm_hmma<<<grid_gh, blk256>>>(w1, x, nullptr, nullptr, p_y, nullptr);
    bn_finalize_kernel<<<1, CC>>>(g1, b1);
    bn_apply_kernel<<<grid_ba, blk256>>>(p_y, p_h, nullptr, 0);

    gemm_hmma<<<grid_gh, blk256>>>(w2, p_h, nullptr, nullptr, p_y, nullptr);
    bn_finalize_kernel<<<1, CC>>>(g2, b2);
    bn_apply_kernel<<<grid_ba, blk256>>>(p_y, p_h, nullptr, 0);

    // 4 offset-attention layers
    for (int i = 0; i < 4; i++) {
        gemm_qk<<<grid_qk, blk256>>>(wqk + (size_t)i * 32 * CC, p_h, p_qh, p_ql, p_qth, p_qtl);
        energy_softmax<<<grid_es, blk256>>>(p_qh, p_ql, p_qth, p_qtl, mask, p_u);
        rowscale_kernel<<<grid_rs, blk256>>>();
        gemm_hmma<<<grid_gh, blk256>>>(wv + (size_t)i * CC * CC, p_h, nullptr, bv + (size_t)i * CC,
                                       nullptr, p_xvh);
        apply_hmma<<<grid_ap, blk256>>>(p_xvh, p_u, p_xr);
        gemm_hmma<<<grid_gh, blk256>>>(wt + (size_t)i * CC * CC, p_h, p_xr, bt + (size_t)i * CC,
                                       p_y, nullptr);
        bn_finalize_kernel<<<1, CC>>>(sg + (size_t)i * CC, sb + (size_t)i * CC);
        bn_apply_kernel<<<grid_ba, blk256>>>(p_y, p_h, out, i);
    }
}